// round 1
// baseline (speedup 1.0000x reference)
#include <cuda_runtime.h>
#include <math.h>

#define NN      100000
#define EE      1600000
#define NETOT   (EE + NN)           // edges + self loops
#define INC     128
#define C1      128                 // heads(4) * hid(32)
#define C2      64
#define HEADS   4
#define NGRAPH  64
#define NCLS    2
#define NCHUNK  ((NN + 255) / 256)  // 391

// ---------------- scratch (static __device__, no allocations) ----------------
__device__ int   g_deg[NN];
__device__ int   g_rs[NN + 1];
__device__ int   g_cur[NN];
__device__ int   g_csr[NETOT];
__device__ int   g_csum[512];
__device__ float g_h1[NN * C1];
__device__ float g_as1[NN * HEADS];
__device__ float g_ad1[NN * HEADS];
__device__ float g_x2[NN * C1];
__device__ float g_h2[NN * C2];
__device__ float g_as2[NN];
__device__ float g_ad2[NN];
__device__ float g_out2[NN * C2];
__device__ float g_gsum[NGRAPH * C2];
__device__ int   g_gcnt[NGRAPH];

__device__ __forceinline__ float lrelu(float x) { return x > 0.f ? x : 0.2f * x; }
__device__ __forceinline__ float elu1(float x)  { return x > 0.f ? x : expm1f(x); }

// ---------------- CSR build ----------------
__global__ void k_init() {
    int i = blockIdx.x * blockDim.x + threadIdx.x;
    if (i < NN) g_deg[i] = 1;                 // self loop pre-counted
    if (i < NGRAPH * C2) g_gsum[i] = 0.f;
    if (i < NGRAPH) g_gcnt[i] = 0;
}

__global__ void k_hist(const int* __restrict__ dst) {
    int e = blockIdx.x * blockDim.x + threadIdx.x;
    if (e < EE) atomicAdd(&g_deg[dst[e]], 1);
}

__global__ void k_scanA() {
    __shared__ int sh[256];
    int i = blockIdx.x * 256 + threadIdx.x;
    int v = (i < NN) ? g_deg[i] : 0;
    sh[threadIdx.x] = v;
    __syncthreads();
    #pragma unroll
    for (int off = 1; off < 256; off <<= 1) {
        int t = (threadIdx.x >= off) ? sh[threadIdx.x - off] : 0;
        __syncthreads();
        sh[threadIdx.x] += t;
        __syncthreads();
    }
    if (i < NN) g_rs[i] = sh[threadIdx.x] - v;     // chunk-local exclusive
    if (threadIdx.x == 255) g_csum[blockIdx.x] = sh[255];
}

__global__ void k_scanB(int nchunk) {
    __shared__ int sh[512];
    int t = threadIdx.x;
    int v = (t < nchunk) ? g_csum[t] : 0;
    sh[t] = v;
    __syncthreads();
    #pragma unroll
    for (int off = 1; off < 512; off <<= 1) {
        int tv = (t >= off) ? sh[t - off] : 0;
        __syncthreads();
        sh[t] += tv;
        __syncthreads();
    }
    if (t < nchunk) g_csum[t] = sh[t] - v;         // exclusive
}

__global__ void k_scanC() {
    int i = blockIdx.x * 256 + threadIdx.x;
    if (i < NN) {
        int r = g_rs[i] + g_csum[blockIdx.x];
        g_rs[i] = r;
        g_cur[i] = r;
    }
    if (i == 0) g_rs[NN] = NETOT;
}

__global__ void k_scatter(const int* __restrict__ ei) {
    int idx = blockIdx.x * blockDim.x + threadIdx.x;
    if (idx >= NETOT) return;
    int s, d;
    if (idx < EE) { s = ei[idx]; d = ei[EE + idx]; }
    else          { s = idx - EE; d = s; }
    int pos = atomicAdd(&g_cur[d], 1);
    g_csr[pos] = s;
}

// ---------------- GEMM1: h1 = x @ W1  (+ per-node attention scalars) ----------------
// block: 64 threads, 8 rows; thread t handles cols t and t+64
__global__ void k_gemm1(const float* __restrict__ x, const float* __restrict__ W1,
                        const float* __restrict__ att_s, const float* __restrict__ att_d) {
    __shared__ float xs[8][INC];
    int t = threadIdx.x;
    int row0 = blockIdx.x * 8;
    int nrows = NN - row0; if (nrows > 8) nrows = 8;
    for (int i = t; i < nrows * INC; i += 64) xs[i / INC][i % INC] = x[row0 * INC + i];
    __syncthreads();

    float acc0[8], acc1[8];
    #pragma unroll
    for (int r = 0; r < 8; r++) { acc0[r] = 0.f; acc1[r] = 0.f; }
    #pragma unroll 4
    for (int k = 0; k < INC; k++) {
        float w0 = W1[k * C1 + t];
        float w1 = W1[k * C1 + t + 64];
        #pragma unroll
        for (int r = 0; r < 8; r++) {
            float xv = xs[r][k];
            acc0[r] += xv * w0;
            acc1[r] += xv * w1;
        }
    }
    int w = t >> 5, lane = t & 31;
    float as0 = att_s[t], as1 = att_s[64 + t];
    float ad0 = att_d[t], ad1 = att_d[64 + t];
    for (int r = 0; r < nrows; r++) {
        int row = row0 + r;
        g_h1[row * C1 + t]      = acc0[r];
        g_h1[row * C1 + t + 64] = acc1[r];
        float s0 = acc0[r] * as0, s1 = acc1[r] * as1;
        float d0 = acc0[r] * ad0, d1 = acc1[r] * ad1;
        #pragma unroll
        for (int o = 16; o; o >>= 1) {
            s0 += __shfl_xor_sync(0xffffffffu, s0, o);
            s1 += __shfl_xor_sync(0xffffffffu, s1, o);
            d0 += __shfl_xor_sync(0xffffffffu, d0, o);
            d1 += __shfl_xor_sync(0xffffffffu, d1, o);
        }
        if (lane == 0) {
            g_as1[row * 4 + w]     = s0;
            g_as1[row * 4 + w + 2] = s1;
            g_ad1[row * 4 + w]     = d0;
            g_ad1[row * 4 + w + 2] = d1;
        }
    }
}

// ---------------- conv1 aggregation: one warp per destination node ----------------
__global__ void k_agg1(const float* __restrict__ b1) {
    int gw = (blockIdx.x * blockDim.x + threadIdx.x) >> 5;
    if (gw >= NN) return;
    int lane = threadIdx.x & 31;
    int node = gw;
    int beg = g_rs[node], end = g_rs[node + 1];
    float4 ad = *(const float4*)(g_ad1 + node * 4);

    // pass A: per-head max over incoming edges (lanes stride edges)
    float m0 = -1e30f, m1 = -1e30f, m2 = -1e30f, m3 = -1e30f;
    for (int j = beg + lane; j < end; j += 32) {
        int s = g_csr[j];
        float4 as = *(const float4*)(g_as1 + s * 4);
        m0 = fmaxf(m0, lrelu(as.x + ad.x));
        m1 = fmaxf(m1, lrelu(as.y + ad.y));
        m2 = fmaxf(m2, lrelu(as.z + ad.z));
        m3 = fmaxf(m3, lrelu(as.w + ad.w));
    }
    #pragma unroll
    for (int o = 16; o; o >>= 1) {
        m0 = fmaxf(m0, __shfl_xor_sync(0xffffffffu, m0, o));
        m1 = fmaxf(m1, __shfl_xor_sync(0xffffffffu, m1, o));
        m2 = fmaxf(m2, __shfl_xor_sync(0xffffffffu, m2, o));
        m3 = fmaxf(m3, __shfl_xor_sync(0xffffffffu, m3, o));
    }
    int head = lane >> 3;  // lane covers cols [4*lane, 4*lane+4), head = lane/8
    float mh  = head == 0 ? m0   : head == 1 ? m1   : head == 2 ? m2   : m3;
    float adh = head == 0 ? ad.x : head == 1 ? ad.y : head == 2 ? ad.z : ad.w;

    // pass B: weighted sum (softmax numerator + denominator), serial over edges
    float sum = 0.f;
    float4 acc = make_float4(0.f, 0.f, 0.f, 0.f);
    for (int j = beg; j < end; j++) {
        int s = g_csr[j];
        float asv = g_as1[s * 4 + head];
        float e = __expf(lrelu(asv + adh) - mh);
        sum += e;
        float4 hv = *(const float4*)(g_h1 + s * C1 + lane * 4);
        acc.x += e * hv.x; acc.y += e * hv.y; acc.z += e * hv.z; acc.w += e * hv.w;
    }
    float inv = 1.0f / (sum + 1e-16f);
    float4 bv = *(const float4*)(b1 + lane * 4);
    float4 o;
    o.x = elu1(acc.x * inv + bv.x);
    o.y = elu1(acc.y * inv + bv.y);
    o.z = elu1(acc.z * inv + bv.z);
    o.w = elu1(acc.w * inv + bv.w);
    *(float4*)(g_x2 + node * C1 + lane * 4) = o;
}

// ---------------- GEMM2: h2 = x2 @ W2 (+ attention scalars) ----------------
// block: 32 threads, 16 rows; thread lane handles cols lane and lane+32
__global__ void k_gemm2(const float* __restrict__ W2,
                        const float* __restrict__ att_s, const float* __restrict__ att_d) {
    __shared__ float xs[16][C1];
    int lane = threadIdx.x;
    int row0 = blockIdx.x * 16;
    int nrows = NN - row0; if (nrows > 16) nrows = 16;
    for (int i = lane; i < nrows * C1; i += 32) xs[i / C1][i % C1] = g_x2[row0 * C1 + i];
    __syncthreads();

    float acc0[16], acc1[16];
    #pragma unroll
    for (int r = 0; r < 16; r++) { acc0[r] = 0.f; acc1[r] = 0.f; }
    #pragma unroll 2
    for (int k = 0; k < C1; k++) {
        float w0 = W2[k * C2 + lane];
        float w1 = W2[k * C2 + lane + 32];
        #pragma unroll
        for (int r = 0; r < 16; r++) {
            float xv = xs[r][k];
            acc0[r] += xv * w0;
            acc1[r] += xv * w1;
        }
    }
    float as0 = att_s[lane], as1 = att_s[lane + 32];
    float ad0 = att_d[lane], ad1 = att_d[lane + 32];
    for (int r = 0; r < nrows; r++) {
        int row = row0 + r;
        g_h2[row * C2 + lane]      = acc0[r];
        g_h2[row * C2 + lane + 32] = acc1[r];
        float sv = acc0[r] * as0 + acc1[r] * as1;
        float dv = acc0[r] * ad0 + acc1[r] * ad1;
        #pragma unroll
        for (int o = 16; o; o >>= 1) {
            sv += __shfl_xor_sync(0xffffffffu, sv, o);
            dv += __shfl_xor_sync(0xffffffffu, dv, o);
        }
        if (lane == 0) { g_as2[row] = sv; g_ad2[row] = dv; }
    }
}

// ---------------- conv2 aggregation: one warp per node ----------------
__global__ void k_agg2(const float* __restrict__ b2) {
    int gw = (blockIdx.x * blockDim.x + threadIdx.x) >> 5;
    if (gw >= NN) return;
    int lane = threadIdx.x & 31;
    int node = gw;
    int beg = g_rs[node], end = g_rs[node + 1];
    float ad = g_ad2[node];

    float m = -1e30f;
    for (int j = beg + lane; j < end; j += 32)
        m = fmaxf(m, lrelu(g_as2[g_csr[j]] + ad));
    #pragma unroll
    for (int o = 16; o; o >>= 1) m = fmaxf(m, __shfl_xor_sync(0xffffffffu, m, o));

    float sum = 0.f;
    float2 acc = make_float2(0.f, 0.f);
    for (int j = beg; j < end; j++) {
        int s = g_csr[j];
        float e = __expf(lrelu(g_as2[s] + ad) - m);
        sum += e;
        float2 hv = *(const float2*)(g_h2 + s * C2 + lane * 2);
        acc.x += e * hv.x; acc.y += e * hv.y;
    }
    float inv = 1.0f / (sum + 1e-16f);
    float2 bv = *(const float2*)(b2 + lane * 2);
    float2 o;
    o.x = elu1(acc.x * inv + bv.x);
    o.y = elu1(acc.y * inv + bv.y);
    *(float2*)(g_out2 + node * C2 + lane * 2) = o;
}

// ---------------- global mean pool (batch sorted) ----------------
#define POOL_CHUNK 512
__global__ void k_pool(const int* __restrict__ batch) {
    int t = threadIdx.x;  // 64 threads = 64 channels
    int n0 = blockIdx.x * POOL_CHUNK;
    if (n0 >= NN) return;
    int n1 = n0 + POOL_CHUNK; if (n1 > NN) n1 = NN;
    float acc = 0.f;
    int cnt = 0;
    int g = batch[n0];
    for (int n = n0; n < n1; n++) {
        int gn = batch[n];
        if (gn != g) {
            atomicAdd(&g_gsum[g * C2 + t], acc);
            if (t == 0) atomicAdd(&g_gcnt[g], cnt);
            acc = 0.f; cnt = 0; g = gn;
        }
        acc += g_out2[n * C2 + t];
        cnt++;
    }
    atomicAdd(&g_gsum[g * C2 + t], acc);
    if (t == 0) atomicAdd(&g_gcnt[g], cnt);
}

// ---------------- classifier ----------------
__global__ void k_final(const float* __restrict__ Wc, const float* __restrict__ bc,
                        float* __restrict__ out) {
    int t = threadIdx.x;
    if (t >= NGRAPH * NCLS) return;
    int gph = t >> 1, k = t & 1;
    float cnt = (float)g_gcnt[gph];
    if (cnt < 1.f) cnt = 1.f;
    float s = 0.f;
    #pragma unroll
    for (int c = 0; c < C2; c++) s += g_gsum[gph * C2 + c] * Wc[c * NCLS + k];
    out[t] = s / cnt + bc[k];
}

// ---------------- launch ----------------
extern "C" void kernel_launch(void* const* d_in, const int* in_sizes, int n_in,
                              void* d_out, int out_size) {
    const float* x     = (const float*)d_in[0];
    const int*   ei    = (const int*)  d_in[1];   // [2, E] row-major
    const int*   batch = (const int*)  d_in[2];
    const float* W1    = (const float*)d_in[3];
    const float* atts1 = (const float*)d_in[4];
    const float* attd1 = (const float*)d_in[5];
    const float* b1    = (const float*)d_in[6];
    const float* W2    = (const float*)d_in[7];
    const float* atts2 = (const float*)d_in[8];
    const float* attd2 = (const float*)d_in[9];
    const float* b2    = (const float*)d_in[10];
    const float* Wc    = (const float*)d_in[11];
    const float* bc    = (const float*)d_in[12];
    float* out = (float*)d_out;

    k_init   <<<(NN + 255) / 256, 256>>>();
    k_hist   <<<(EE + 255) / 256, 256>>>(ei + EE);
    k_scanA  <<<NCHUNK, 256>>>();
    k_scanB  <<<1, 512>>>(NCHUNK);
    k_scanC  <<<NCHUNK, 256>>>();
    k_scatter<<<(NETOT + 255) / 256, 256>>>(ei);

    k_gemm1  <<<(NN + 7) / 8, 64>>>(x, W1, atts1, attd1);
    k_agg1   <<<(NN * 32 + 255) / 256, 256>>>(b1);

    k_gemm2  <<<(NN + 15) / 16, 32>>>(W2, atts2, attd2);
    k_agg2   <<<(NN * 32 + 255) / 256, 256>>>(b2);

    k_pool   <<<(NN + POOL_CHUNK - 1) / POOL_CHUNK, 64>>>(batch);
    k_final  <<<1, 128>>>(Wc, bc, out);
}

// round 2
// speedup vs baseline: 1.4354x; 1.4354x over previous
#include <cuda_runtime.h>
#include <cuda_fp16.h>
#include <math.h>

#define NN      100000
#define EE      1600000
#define NETOT   (EE + NN)           // edges + self loops
#define INC     128
#define C1      128                 // heads(4) * hid(32)
#define C2      64
#define HEADS   4
#define NGRAPH  64
#define NCLS    2
#define NCHUNK  ((NN + 255) / 256)  // 391
#define POOL_CHUNK 128

// ---------------- scratch (static __device__, no allocations) ----------------
__device__ int    g_deg[NN];
__device__ int    g_rs[NN + 1];
__device__ int    g_cur[NN];
__device__ int    g_csr[NETOT];
__device__ int    g_csum[512];
__device__ __half g_h1h[NN * C1];
__device__ float  g_as1[NN * HEADS];
__device__ float  g_ad1[NN * HEADS];
__device__ float  g_x2[NN * C1];
__device__ __half g_h2h[NN * C2];
__device__ float  g_as2[NN];
__device__ float  g_ad2[NN];
__device__ float  g_out2[NN * C2];
__device__ float  g_gsum[NGRAPH * C2];
__device__ int    g_gcnt[NGRAPH];

__device__ __forceinline__ float lrelu(float x) { return x > 0.f ? x : 0.2f * x; }
__device__ __forceinline__ float elu1(float x)  { return x > 0.f ? x : expm1f(x); }

// packed f32x2 FMA (FFMA2) — ptxas never emits this from C++
__device__ __forceinline__ void ffma2(unsigned long long& acc,
                                      unsigned long long ab, unsigned long long w) {
    asm("fma.rn.f32x2 %0, %1, %2, %0;" : "+l"(acc) : "l"(ab), "l"(w));
}
__device__ __forceinline__ unsigned long long bcast2(float v) {
    unsigned long long r;
    asm("mov.b64 %0, {%1, %1};" : "=l"(r) : "f"(v));
    return r;
}

// ---------------- CSR build ----------------
__global__ void k_init() {
    int i = blockIdx.x * blockDim.x + threadIdx.x;
    if (i < NN) g_deg[i] = 1;                 // self loop pre-counted
    if (i < NGRAPH * C2) g_gsum[i] = 0.f;
    if (i < NGRAPH) g_gcnt[i] = 0;
}

__global__ void k_hist(const int* __restrict__ dst) {
    int e4 = blockIdx.x * blockDim.x + threadIdx.x;
    if (e4 * 4 + 3 < EE) {
        int4 d = *(const int4*)(dst + e4 * 4);
        atomicAdd(&g_deg[d.x], 1);
        atomicAdd(&g_deg[d.y], 1);
        atomicAdd(&g_deg[d.z], 1);
        atomicAdd(&g_deg[d.w], 1);
    } else {
        for (int e = e4 * 4; e < EE; e++) atomicAdd(&g_deg[dst[e]], 1);
    }
}

__global__ void k_scanA() {
    __shared__ int sh[256];
    int i = blockIdx.x * 256 + threadIdx.x;
    int v = (i < NN) ? g_deg[i] : 0;
    sh[threadIdx.x] = v;
    __syncthreads();
    #pragma unroll
    for (int off = 1; off < 256; off <<= 1) {
        int t = (threadIdx.x >= off) ? sh[threadIdx.x - off] : 0;
        __syncthreads();
        sh[threadIdx.x] += t;
        __syncthreads();
    }
    if (i < NN) g_rs[i] = sh[threadIdx.x] - v;     // chunk-local exclusive
    if (threadIdx.x == 255) g_csum[blockIdx.x] = sh[255];
}

__global__ void k_scanB(int nchunk) {
    __shared__ int sh[512];
    int t = threadIdx.x;
    int v = (t < nchunk) ? g_csum[t] : 0;
    sh[t] = v;
    __syncthreads();
    #pragma unroll
    for (int off = 1; off < 512; off <<= 1) {
        int tv = (t >= off) ? sh[t - off] : 0;
        __syncthreads();
        sh[t] += tv;
        __syncthreads();
    }
    if (t < nchunk) g_csum[t] = sh[t] - v;         // exclusive
}

__global__ void k_scanC() {
    int i = blockIdx.x * 256 + threadIdx.x;
    if (i < NN) {
        int r = g_rs[i] + g_csum[blockIdx.x];
        g_rs[i] = r;
        g_cur[i] = r;
    }
    if (i == 0) g_rs[NN] = NETOT;
}

__global__ void k_scatter(const int* __restrict__ ei) {
    int idx = blockIdx.x * blockDim.x + threadIdx.x;
    if (idx >= NETOT) return;
    int s, d;
    if (idx < EE) { s = ei[idx]; d = ei[EE + idx]; }
    else          { s = idx - EE; d = s; }
    int pos = atomicAdd(&g_cur[d], 1);
    g_csr[pos] = s;
}

// ---------------- GEMM1: h1 = x @ W1 (fp16 out) + attention scalars ----------------
// 64 threads, 8 rows/block; thread t owns cols 2t, 2t+1; FFMA2 over row pairs.
__global__ void k_gemm1(const float* __restrict__ x, const float* __restrict__ W1,
                        const float* __restrict__ att_s, const float* __restrict__ att_d) {
    __shared__ __align__(16) float xs[INC][10];   // [k][r], padded (2-way conflicts)
    int t = threadIdx.x;
    int row0 = blockIdx.x * 8;                    // 100000/8 = 12500 exact
    for (int i = t; i < 8 * INC; i += 64) {
        int r = i >> 7, k = i & 127;
        xs[k][r] = x[(row0 + r) * INC + k];
    }
    __syncthreads();

    unsigned long long a0[4] = {0,0,0,0}, a1[4] = {0,0,0,0};
    #pragma unroll 4
    for (int k = 0; k < INC; k++) {
        float2 w = *(const float2*)(W1 + k * C1 + 2 * t);
        unsigned long long w0 = bcast2(w.x), w1 = bcast2(w.y);
        const unsigned long long* xp = (const unsigned long long*)xs[k];
        #pragma unroll
        for (int i = 0; i < 4; i++) { ffma2(a0[i], xp[i], w0); ffma2(a1[i], xp[i], w1); }
    }
    const float* v0 = (const float*)a0;   // v0[r] = row r, col 2t
    const float* v1 = (const float*)a1;   // v1[r] = row r, col 2t+1

    int lane = t & 31;
    int head = t >> 4;                    // cols [32*head, 32*head+32)
    float as0 = att_s[2 * t], as1 = att_s[2 * t + 1];
    float ad0 = att_d[2 * t], ad1 = att_d[2 * t + 1];
    #pragma unroll
    for (int r = 0; r < 8; r++) {
        int row = row0 + r;
        *(__half2*)(g_h1h + row * C1 + 2 * t) = __floats2half2_rn(v0[r], v1[r]);
        float s = v0[r] * as0 + v1[r] * as1;
        float d = v0[r] * ad0 + v1[r] * ad1;
        #pragma unroll
        for (int o = 8; o; o >>= 1) {     // reduce within 16-lane half (one head)
            s += __shfl_xor_sync(0xffffffffu, s, o);
            d += __shfl_xor_sync(0xffffffffu, d, o);
        }
        if ((lane & 15) == 0) {
            g_as1[row * 4 + head] = s;
            g_ad1[row * 4 + head] = d;
        }
    }
}

// ---------------- conv1 aggregation: one warp per dst node, single pass ----------------
__global__ void k_agg1(const float* __restrict__ b1) {
    int gw = (blockIdx.x * blockDim.x + threadIdx.x) >> 5;
    if (gw >= NN) return;
    int lane = threadIdx.x & 31;
    int beg = g_rs[gw], end = g_rs[gw + 1];
    int head = lane >> 3;                 // lane covers cols [4*lane, 4*lane+4)
    float adh = g_ad1[gw * 4 + head];

    float sum = 0.f;
    float4 acc = make_float4(0.f, 0.f, 0.f, 0.f);
    for (int j = beg; j < end; j++) {
        int s = g_csr[j];
        float e = __expf(lrelu(g_as1[s * 4 + head] + adh));
        sum += e;
        uint2 u = *(const uint2*)(g_h1h + s * C1 + lane * 4);
        float2 f01 = __half22float2(*(__half2*)&u.x);
        float2 f23 = __half22float2(*(__half2*)&u.y);
        acc.x += e * f01.x; acc.y += e * f01.y;
        acc.z += e * f23.x; acc.w += e * f23.y;
    }
    float inv = 1.0f / (sum + 1e-16f);
    float4 bv = *(const float4*)(b1 + lane * 4);
    float4 o;
    o.x = elu1(acc.x * inv + bv.x);
    o.y = elu1(acc.y * inv + bv.y);
    o.z = elu1(acc.z * inv + bv.z);
    o.w = elu1(acc.w * inv + bv.w);
    *(float4*)(g_x2 + gw * C1 + lane * 4) = o;
}

// ---------------- GEMM2: h2 = x2 @ W2 (fp16 out) + attention scalars ----------------
// 32 threads, 16 rows/block; thread t owns cols 2t, 2t+1.
__global__ void k_gemm2(const float* __restrict__ W2,
                        const float* __restrict__ att_s, const float* __restrict__ att_d) {
    __shared__ __align__(16) float xs[C1][18];    // padded (2-way conflicts)
    int t = threadIdx.x;
    int row0 = blockIdx.x * 16;                   // 100000/16 = 6250 exact
    for (int i = t; i < 16 * C1; i += 32) {
        int r = i >> 7, k = i & 127;
        xs[k][r] = g_x2[(row0 + r) * C1 + k];
    }
    __syncthreads();

    unsigned long long a0[8] = {0,0,0,0,0,0,0,0}, a1[8] = {0,0,0,0,0,0,0,0};
    #pragma unroll 2
    for (int k = 0; k < C1; k++) {
        float2 w = *(const float2*)(W2 + k * C2 + 2 * t);
        unsigned long long w0 = bcast2(w.x), w1 = bcast2(w.y);
        const unsigned long long* xp = (const unsigned long long*)xs[k];
        #pragma unroll
        for (int i = 0; i < 8; i++) { ffma2(a0[i], xp[i], w0); ffma2(a1[i], xp[i], w1); }
    }
    const float* v0 = (const float*)a0;
    const float* v1 = (const float*)a1;

    float as0 = att_s[2 * t], as1 = att_s[2 * t + 1];
    float ad0 = att_d[2 * t], ad1 = att_d[2 * t + 1];
    #pragma unroll
    for (int r = 0; r < 16; r++) {
        int row = row0 + r;
        *(__half2*)(g_h2h + row * C2 + 2 * t) = __floats2half2_rn(v0[r], v1[r]);
        float s = v0[r] * as0 + v1[r] * as1;
        float d = v0[r] * ad0 + v1[r] * ad1;
        #pragma unroll
        for (int o = 16; o; o >>= 1) {
            s += __shfl_xor_sync(0xffffffffu, s, o);
            d += __shfl_xor_sync(0xffffffffu, d, o);
        }
        if (t == 0) { g_as2[row] = s; g_ad2[row] = d; }
    }
}

// ---------------- conv2 aggregation: one warp per node, single pass ----------------
__global__ void k_agg2(const float* __restrict__ b2) {
    int gw = (blockIdx.x * blockDim.x + threadIdx.x) >> 5;
    if (gw >= NN) return;
    int lane = threadIdx.x & 31;
    int beg = g_rs[gw], end = g_rs[gw + 1];
    float ad = g_ad2[gw];

    float sum = 0.f;
    float2 acc = make_float2(0.f, 0.f);
    for (int j = beg; j < end; j++) {
        int s = g_csr[j];
        float e = __expf(lrelu(g_as2[s] + ad));
        sum += e;
        float2 f = __half22float2(*(const __half2*)(g_h2h + s * C2 + lane * 2));
        acc.x += e * f.x; acc.y += e * f.y;
    }
    float inv = 1.0f / (sum + 1e-16f);
    float2 bv = *(const float2*)(b2 + lane * 2);
    float2 o;
    o.x = elu1(acc.x * inv + bv.x);
    o.y = elu1(acc.y * inv + bv.y);
    *(float2*)(g_out2 + gw * C2 + lane * 2) = o;
}

// ---------------- global mean pool (batch sorted) ----------------
__global__ void k_pool(const int* __restrict__ batch) {
    int t = threadIdx.x;  // 64 threads = 64 channels
    int n0 = blockIdx.x * POOL_CHUNK;
    if (n0 >= NN) return;
    int n1 = n0 + POOL_CHUNK; if (n1 > NN) n1 = NN;
    float acc = 0.f;
    int cnt = 0;
    int g = batch[n0];
    for (int n = n0; n < n1; n++) {
        int gn = batch[n];
        if (gn != g) {
            atomicAdd(&g_gsum[g * C2 + t], acc);
            if (t == 0) atomicAdd(&g_gcnt[g], cnt);
            acc = 0.f; cnt = 0; g = gn;
        }
        acc += g_out2[n * C2 + t];
        cnt++;
    }
    atomicAdd(&g_gsum[g * C2 + t], acc);
    if (t == 0) atomicAdd(&g_gcnt[g], cnt);
}

// ---------------- classifier ----------------
__global__ void k_final(const float* __restrict__ Wc, const float* __restrict__ bc,
                        float* __restrict__ out) {
    int t = threadIdx.x;
    if (t >= NGRAPH * NCLS) return;
    int gph = t >> 1, k = t & 1;
    float cnt = (float)g_gcnt[gph];
    if (cnt < 1.f) cnt = 1.f;
    float s = 0.f;
    #pragma unroll
    for (int c = 0; c < C2; c++) s += g_gsum[gph * C2 + c] * Wc[c * NCLS + k];
    out[t] = s / cnt + bc[k];
}

// ---------------- launch ----------------
extern "C" void kernel_launch(void* const* d_in, const int* in_sizes, int n_in,
                              void* d_out, int out_size) {
    const float* x     = (const float*)d_in[0];
    const int*   ei    = (const int*)  d_in[1];   // [2, E] row-major
    const int*   batch = (const int*)  d_in[2];
    const float* W1    = (const float*)d_in[3];
    const float* atts1 = (const float*)d_in[4];
    const float* attd1 = (const float*)d_in[5];
    const float* b1    = (const float*)d_in[6];
    const float* W2    = (const float*)d_in[7];
    const float* atts2 = (const float*)d_in[8];
    const float* attd2 = (const float*)d_in[9];
    const float* b2    = (const float*)d_in[10];
    const float* Wc    = (const float*)d_in[11];
    const float* bc    = (const float*)d_in[12];
    float* out = (float*)d_out;

    // order chosen so the heavy gemm1 sits at launch index 3 (ncu captures it)
    k_init   <<<(NN + 255) / 256, 256>>>();
    k_hist   <<<(EE / 4 + 255) / 256, 256>>>(ei + EE);
    k_scanA  <<<NCHUNK, 256>>>();
    k_gemm1  <<<NN / 8, 64>>>(x, W1, atts1, attd1);
    k_scanB  <<<1, 512>>>(NCHUNK);
    k_scanC  <<<NCHUNK, 256>>>();
    k_scatter<<<(NETOT + 255) / 256, 256>>>(ei);

    k_agg1   <<<(NN * 32 + 255) / 256, 256>>>(b1);
    k_gemm2  <<<NN / 16, 32>>>(W2, atts2, attd2);
    k_agg2   <<<(NN * 32 + 255) / 256, 256>>>(b2);

    k_pool   <<<(NN + POOL_CHUNK - 1) / POOL_CHUNK, 64>>>(batch);
    k_final  <<<1, 128>>>(Wc, bc, out);
}

// round 3
// speedup vs baseline: 1.5154x; 1.0557x over previous
#include <cuda_runtime.h>
#include <cuda_fp16.h>
#include <math.h>

#define NN      100000
#define EE      1600000
#define NETOT   (EE + NN)           // edges + self loops
#define INC     128
#define C1      128                 // heads(4) * hid(32)
#define C2      64
#define HEADS   4
#define NGRAPH  64
#define NCLS    2
#define NCHUNK  ((NN + 255) / 256)  // 391
#define POOL_CHUNK 128
#define G_ROWS  32                  // rows per gemm block (2 warps x 16)
#define XS_STRIDE (G_ROWS + 4)      // 36: multiple of 4 (LDS.128 align), kills STS conflicts

// ---------------- scratch (static __device__, no allocations) ----------------
__device__ int    g_deg[NN];
__device__ int    g_rs[NN + 1];
__device__ int    g_cur[NN];
__device__ int    g_csr[NETOT];
__device__ int    g_csum[512];
__device__ __half g_h1h[NN * C1];
__device__ float  g_as1[NN * HEADS];
__device__ float  g_ad1[NN * HEADS];
__device__ float  g_x2[NN * C1];
__device__ __half g_h2h[NN * C2];
__device__ float  g_as2[NN];
__device__ float  g_ad2[NN];
__device__ float  g_out2[NN * C2];
__device__ float  g_gsum[NGRAPH * C2];
__device__ int    g_gcnt[NGRAPH];

__device__ __forceinline__ float lrelu(float x) { return x > 0.f ? x : 0.2f * x; }
__device__ __forceinline__ float elu1(float x)  { return x > 0.f ? x : expm1f(x); }

// packed f32x2 FMA (FFMA2) — ptxas never emits this from C++
__device__ __forceinline__ void ffma2(unsigned long long& acc,
                                      unsigned long long ab, unsigned long long w) {
    asm("fma.rn.f32x2 %0, %1, %2, %0;" : "+l"(acc) : "l"(ab), "l"(w));
}
__device__ __forceinline__ unsigned long long bcast2(float v) {
    unsigned long long r;
    asm("mov.b64 %0, {%1, %1};" : "=l"(r) : "f"(v));
    return r;
}

// ---------------- CSR build ----------------
__global__ void k_init() {
    int i = blockIdx.x * blockDim.x + threadIdx.x;
    if (i < NN) g_deg[i] = 1;                 // self loop pre-counted
    if (i < NGRAPH * C2) g_gsum[i] = 0.f;
    if (i < NGRAPH) g_gcnt[i] = 0;
}

__global__ void k_hist(const int* __restrict__ dst) {
    int e4 = blockIdx.x * blockDim.x + threadIdx.x;
    if (e4 * 4 + 3 < EE) {
        int4 d = *(const int4*)(dst + e4 * 4);
        atomicAdd(&g_deg[d.x], 1);
        atomicAdd(&g_deg[d.y], 1);
        atomicAdd(&g_deg[d.z], 1);
        atomicAdd(&g_deg[d.w], 1);
    } else {
        for (int e = e4 * 4; e < EE; e++) atomicAdd(&g_deg[dst[e]], 1);
    }
}

__global__ void k_scanA() {
    __shared__ int sh[256];
    int i = blockIdx.x * 256 + threadIdx.x;
    int v = (i < NN) ? g_deg[i] : 0;
    sh[threadIdx.x] = v;
    __syncthreads();
    #pragma unroll
    for (int off = 1; off < 256; off <<= 1) {
        int t = (threadIdx.x >= off) ? sh[threadIdx.x - off] : 0;
        __syncthreads();
        sh[threadIdx.x] += t;
        __syncthreads();
    }
    if (i < NN) g_rs[i] = sh[threadIdx.x] - v;     // chunk-local exclusive
    if (threadIdx.x == 255) g_csum[blockIdx.x] = sh[255];
}

__global__ void k_scanB(int nchunk) {
    __shared__ int sh[512];
    int t = threadIdx.x;
    int v = (t < nchunk) ? g_csum[t] : 0;
    sh[t] = v;
    __syncthreads();
    #pragma unroll
    for (int off = 1; off < 512; off <<= 1) {
        int tv = (t >= off) ? sh[t - off] : 0;
        __syncthreads();
        sh[t] += tv;
        __syncthreads();
    }
    if (t < nchunk) g_csum[t] = sh[t] - v;         // exclusive
}

__global__ void k_scanC() {
    int i = blockIdx.x * 256 + threadIdx.x;
    if (i < NN) {
        int r = g_rs[i] + g_csum[blockIdx.x];
        g_rs[i] = r;
        g_cur[i] = r;
    }
    if (i == 0) g_rs[NN] = NETOT;
}

__global__ void k_scatter(const int* __restrict__ ei) {
    int idx = blockIdx.x * blockDim.x + threadIdx.x;
    if (idx >= NETOT) return;
    int s, d;
    if (idx < EE) { s = ei[idx]; d = ei[EE + idx]; }
    else          { s = idx - EE; d = s; }
    int pos = atomicAdd(&g_cur[d], 1);
    g_csr[pos] = s;
}

// ---------------- GEMM1: h1 = x @ W1 (fp16 out) + attention scalars ----------------
// block: 64 threads = 2 warps; 32 rows/block; warp w -> rows 16w..16w+15,
// thread lane -> cols 4*lane..4*lane+3. xs transposed [k][row], broadcast LDS.128.
__global__ void __launch_bounds__(64) k_gemm1(
        const float* __restrict__ x, const float* __restrict__ W1,
        const float* __restrict__ att_s, const float* __restrict__ att_d) {
    __shared__ __align__(16) float xs[INC][XS_STRIDE];
    int t = threadIdx.x;
    int w = t >> 5, lane = t & 31;
    int row0 = blockIdx.x * G_ROWS;               // 100000/32 = 3125 exact

    // prologue: transpose 32x128 tile into xs[k][r]; conflict-free STS
    {
        int r = t & 31;
        int kc = (t >> 5) * 64;
        const float* xr = x + (row0 + r) * INC + kc;
        #pragma unroll
        for (int i = 0; i < 16; i++) {
            float4 v = *(const float4*)(xr + 4 * i);
            xs[kc + 4 * i + 0][r] = v.x;
            xs[kc + 4 * i + 1][r] = v.y;
            xs[kc + 4 * i + 2][r] = v.z;
            xs[kc + 4 * i + 3][r] = v.w;
        }
    }
    __syncthreads();

    int rbase = 16 * w;
    unsigned long long acc[8][4];                  // [row-pair][col]
    #pragma unroll
    for (int p = 0; p < 8; p++)
        #pragma unroll
        for (int c = 0; c < 4; c++) acc[p][c] = 0ull;

    #pragma unroll 8
    for (int k = 0; k < INC; k++) {
        float4 wv = *(const float4*)(W1 + k * C1 + 4 * lane);
        unsigned long long wb0 = bcast2(wv.x), wb1 = bcast2(wv.y);
        unsigned long long wb2 = bcast2(wv.z), wb3 = bcast2(wv.w);
        #pragma unroll
        for (int j = 0; j < 4; j++) {
            float4 xv = *(const float4*)&xs[k][rbase + 4 * j];   // broadcast
            unsigned long long p0 = *(unsigned long long*)&xv.x;
            unsigned long long p1 = *(unsigned long long*)&xv.z;
            ffma2(acc[2*j  ][0], p0, wb0); ffma2(acc[2*j  ][1], p0, wb1);
            ffma2(acc[2*j  ][2], p0, wb2); ffma2(acc[2*j  ][3], p0, wb3);
            ffma2(acc[2*j+1][0], p1, wb0); ffma2(acc[2*j+1][1], p1, wb1);
            ffma2(acc[2*j+1][2], p1, wb2); ffma2(acc[2*j+1][3], p1, wb3);
        }
    }

    int head = lane >> 3;                          // cols [32*head, 32*head+32)
    float4 asv = *(const float4*)(att_s + 4 * lane);
    float4 adv = *(const float4*)(att_d + 4 * lane);
    #pragma unroll
    for (int p = 0; p < 8; p++) {
        #pragma unroll
        for (int h = 0; h < 2; h++) {              // two rows in the pair
            int row = row0 + rbase + 2 * p + h;
            float v0 = ((float*)&acc[p][0])[h];
            float v1 = ((float*)&acc[p][1])[h];
            float v2 = ((float*)&acc[p][2])[h];
            float v3 = ((float*)&acc[p][3])[h];
            __half2 h01 = __floats2half2_rn(v0, v1);
            __half2 h23 = __floats2half2_rn(v2, v3);
            uint2 hh = make_uint2(*(unsigned*)&h01, *(unsigned*)&h23);
            *(uint2*)(g_h1h + row * C1 + 4 * lane) = hh;
            float s = v0 * asv.x + v1 * asv.y + v2 * asv.z + v3 * asv.w;
            float d = v0 * adv.x + v1 * adv.y + v2 * adv.z + v3 * adv.w;
            #pragma unroll
            for (int o = 4; o; o >>= 1) {          // reduce within 8-lane head group
                s += __shfl_xor_sync(0xffffffffu, s, o);
                d += __shfl_xor_sync(0xffffffffu, d, o);
            }
            if ((lane & 7) == 0) {
                g_as1[row * 4 + head] = s;
                g_ad1[row * 4 + head] = d;
            }
        }
    }
}

// ---------------- conv1 aggregation: one warp per dst node, single pass ----------------
__global__ void k_agg1(const float* __restrict__ b1) {
    int gw = (blockIdx.x * blockDim.x + threadIdx.x) >> 5;
    if (gw >= NN) return;
    int lane = threadIdx.x & 31;
    int beg = g_rs[gw], end = g_rs[gw + 1];
    int head = lane >> 3;                 // lane covers cols [4*lane, 4*lane+4)
    float adh = g_ad1[gw * 4 + head];

    float sum = 0.f;
    float4 acc = make_float4(0.f, 0.f, 0.f, 0.f);
    int j = beg;
    for (; j + 2 <= end; j += 2) {
        int s0 = g_csr[j], s1 = g_csr[j + 1];
        float a0 = g_as1[s0 * 4 + head];
        float a1 = g_as1[s1 * 4 + head];
        uint2 u0 = *(const uint2*)(g_h1h + s0 * C1 + lane * 4);
        uint2 u1 = *(const uint2*)(g_h1h + s1 * C1 + lane * 4);
        float e0 = __expf(lrelu(a0 + adh));
        float e1 = __expf(lrelu(a1 + adh));
        sum += e0 + e1;
        float2 f0a = __half22float2(*(__half2*)&u0.x);
        float2 f0b = __half22float2(*(__half2*)&u0.y);
        float2 f1a = __half22float2(*(__half2*)&u1.x);
        float2 f1b = __half22float2(*(__half2*)&u1.y);
        acc.x += e0 * f0a.x + e1 * f1a.x;
        acc.y += e0 * f0a.y + e1 * f1a.y;
        acc.z += e0 * f0b.x + e1 * f1b.x;
        acc.w += e0 * f0b.y + e1 * f1b.y;
    }
    if (j < end) {
        int s = g_csr[j];
        float e = __expf(lrelu(g_as1[s * 4 + head] + adh));
        sum += e;
        uint2 u = *(const uint2*)(g_h1h + s * C1 + lane * 4);
        float2 fa = __half22float2(*(__half2*)&u.x);
        float2 fb = __half22float2(*(__half2*)&u.y);
        acc.x += e * fa.x; acc.y += e * fa.y;
        acc.z += e * fb.x; acc.w += e * fb.y;
    }
    float inv = 1.0f / (sum + 1e-16f);
    float4 bv = *(const float4*)(b1 + lane * 4);
    float4 o;
    o.x = elu1(acc.x * inv + bv.x);
    o.y = elu1(acc.y * inv + bv.y);
    o.z = elu1(acc.z * inv + bv.z);
    o.w = elu1(acc.w * inv + bv.w);
    *(float4*)(g_x2 + gw * C1 + lane * 4) = o;
}

// ---------------- GEMM2: h2 = x2 @ W2 (fp16 out) + attention scalars ----------------
// block: 64 threads = 2 warps; 32 rows/block; warp w -> rows 16w..+15,
// thread lane -> cols 2*lane, 2*lane+1.
__global__ void __launch_bounds__(64) k_gemm2(
        const float* __restrict__ W2,
        const float* __restrict__ att_s, const float* __restrict__ att_d) {
    __shared__ __align__(16) float xs[C1][XS_STRIDE];
    int t = threadIdx.x;
    int w = t >> 5, lane = t & 31;
    int row0 = blockIdx.x * G_ROWS;               // 3125 blocks exact

    {
        int r = t & 31;
        int kc = (t >> 5) * 64;
        const float* xr = g_x2 + (row0 + r) * C1 + kc;
        #pragma unroll
        for (int i = 0; i < 16; i++) {
            float4 v = *(const float4*)(xr + 4 * i);
            xs[kc + 4 * i + 0][r] = v.x;
            xs[kc + 4 * i + 1][r] = v.y;
            xs[kc + 4 * i + 2][r] = v.z;
            xs[kc + 4 * i + 3][r] = v.w;
        }
    }
    __syncthreads();

    int rbase = 16 * w;
    unsigned long long acc[8][2];
    #pragma unroll
    for (int p = 0; p < 8; p++) { acc[p][0] = 0ull; acc[p][1] = 0ull; }

    #pragma unroll 8
    for (int k = 0; k < C1; k++) {
        float2 wv = *(const float2*)(W2 + k * C2 + 2 * lane);
        unsigned long long wb0 = bcast2(wv.x), wb1 = bcast2(wv.y);
        #pragma unroll
        for (int j = 0; j < 4; j++) {
            float4 xv = *(const float4*)&xs[k][rbase + 4 * j];   // broadcast
            unsigned long long p0 = *(unsigned long long*)&xv.x;
            unsigned long long p1 = *(unsigned long long*)&xv.z;
            ffma2(acc[2*j  ][0], p0, wb0); ffma2(acc[2*j  ][1], p0, wb1);
            ffma2(acc[2*j+1][0], p1, wb0); ffma2(acc[2*j+1][1], p1, wb1);
        }
    }

    float as0 = att_s[2 * lane], as1 = att_s[2 * lane + 1];
    float ad0 = att_d[2 * lane], ad1 = att_d[2 * lane + 1];
    #pragma unroll
    for (int p = 0; p < 8; p++) {
        #pragma unroll
        for (int h = 0; h < 2; h++) {
            int row = row0 + rbase + 2 * p + h;
            float v0 = ((float*)&acc[p][0])[h];
            float v1 = ((float*)&acc[p][1])[h];
            __half2 hv = __floats2half2_rn(v0, v1);
            *(unsigned*)(g_h2h + row * C2 + 2 * lane) = *(unsigned*)&hv;
            float s = v0 * as0 + v1 * as1;
            float d = v0 * ad0 + v1 * ad1;
            #pragma unroll
            for (int o = 16; o; o >>= 1) {
                s += __shfl_xor_sync(0xffffffffu, s, o);
                d += __shfl_xor_sync(0xffffffffu, d, o);
            }
            if (lane == 0) { g_as2[row] = s; g_ad2[row] = d; }
        }
    }
}

// ---------------- conv2 aggregation: one warp per node, single pass ----------------
__global__ void k_agg2(const float* __restrict__ b2) {
    int gw = (blockIdx.x * blockDim.x + threadIdx.x) >> 5;
    if (gw >= NN) return;
    int lane = threadIdx.x & 31;
    int beg = g_rs[gw], end = g_rs[gw + 1];
    float ad = g_ad2[gw];

    float sum = 0.f;
    float2 acc = make_float2(0.f, 0.f);
    int j = beg;
    for (; j + 2 <= end; j += 2) {
        int s0 = g_csr[j], s1 = g_csr[j + 1];
        float a0 = g_as2[s0], a1 = g_as2[s1];
        __half2 u0 = *(const __half2*)(g_h2h + s0 * C2 + lane * 2);
        __half2 u1 = *(const __half2*)(g_h2h + s1 * C2 + lane * 2);
        float e0 = __expf(lrelu(a0 + ad));
        float e1 = __expf(lrelu(a1 + ad));
        sum += e0 + e1;
        float2 f0 = __half22float2(u0);
        float2 f1 = __half22float2(u1);
        acc.x += e0 * f0.x + e1 * f1.x;
        acc.y += e0 * f0.y + e1 * f1.y;
    }
    if (j < end) {
        int s = g_csr[j];
        float e = __expf(lrelu(g_as2[s] + ad));
        sum += e;
        float2 f = __half22float2(*(const __half2*)(g_h2h + s * C2 + lane * 2));
        acc.x += e * f.x; acc.y += e * f.y;
    }
    float inv = 1.0f / (sum + 1e-16f);
    float2 bv = *(const float2*)(b2 + lane * 2);
    float2 o;
    o.x = elu1(acc.x * inv + bv.x);
    o.y = elu1(acc.y * inv + bv.y);
    *(float2*)(g_out2 + gw * C2 + lane * 2) = o;
}

// ---------------- global mean pool (batch sorted) ----------------
__global__ void k_pool(const int* __restrict__ batch) {
    int t = threadIdx.x;  // 64 threads = 64 channels
    int n0 = blockIdx.x * POOL_CHUNK;
    if (n0 >= NN) return;
    int n1 = n0 + POOL_CHUNK; if (n1 > NN) n1 = NN;
    float acc = 0.f;
    int cnt = 0;
    int g = batch[n0];
    for (int n = n0; n < n1; n++) {
        int gn = batch[n];
        if (gn != g) {
            atomicAdd(&g_gsum[g * C2 + t], acc);
            if (t == 0) atomicAdd(&g_gcnt[g], cnt);
            acc = 0.f; cnt = 0; g = gn;
        }
        acc += g_out2[n * C2 + t];
        cnt++;
    }
    atomicAdd(&g_gsum[g * C2 + t], acc);
    if (t == 0) atomicAdd(&g_gcnt[g], cnt);
}

// ---------------- classifier ----------------
__global__ void k_final(const float* __restrict__ Wc, const float* __restrict__ bc,
                        float* __restrict__ out) {
    int t = threadIdx.x;
    if (t >= NGRAPH * NCLS) return;
    int gph = t >> 1, k = t & 1;
    float cnt = (float)g_gcnt[gph];
    if (cnt < 1.f) cnt = 1.f;
    float s = 0.f;
    #pragma unroll
    for (int c = 0; c < C2; c++) s += g_gsum[gph * C2 + c] * Wc[c * NCLS + k];
    out[t] = s / cnt + bc[k];
}

// ---------------- launch ----------------
extern "C" void kernel_launch(void* const* d_in, const int* in_sizes, int n_in,
                              void* d_out, int out_size) {
    const float* x     = (const float*)d_in[0];
    const int*   ei    = (const int*)  d_in[1];   // [2, E] row-major
    const int*   batch = (const int*)  d_in[2];
    const float* W1    = (const float*)d_in[3];
    const float* atts1 = (const float*)d_in[4];
    const float* attd1 = (const float*)d_in[5];
    const float* b1    = (const float*)d_in[6];
    const float* W2    = (const float*)d_in[7];
    const float* atts2 = (const float*)d_in[8];
    const float* attd2 = (const float*)d_in[9];
    const float* b2    = (const float*)d_in[10];
    const float* Wc    = (const float*)d_in[11];
    const float* bc    = (const float*)d_in[12];
    float* out = (float*)d_out;

    // order keeps gemm1 at the launch index ncu captures
    k_init   <<<(NN + 255) / 256, 256>>>();
    k_hist   <<<(EE / 4 + 255) / 256, 256>>>(ei + EE);
    k_scanA  <<<NCHUNK, 256>>>();
    k_gemm1  <<<NN / G_ROWS, 64>>>(x, W1, atts1, attd1);
    k_scanB  <<<1, 512>>>(NCHUNK);
    k_scanC  <<<NCHUNK, 256>>>();
    k_scatter<<<(NETOT + 255) / 256, 256>>>(ei);

    k_agg1   <<<(NN * 32 + 255) / 256, 256>>>(b1);
    k_gemm2  <<<NN / G_ROWS, 64>>>(W2, atts2, attd2);
    k_agg2   <<<(NN * 32 + 255) / 256, 256>>>(b2);

    k_pool   <<<(NN + POOL_CHUNK - 1) / POOL_CHUNK, 64>>>(batch);
    k_final  <<<1, 128>>>(Wc, bc, out);
}

// round 4
// speedup vs baseline: 1.5240x; 1.0057x over previous
#include <cuda_runtime.h>
#include <cuda_fp16.h>
#include <math.h>

#define NN      100000
#define EE      1600000
#define NETOT   (EE + NN)           // edges + self loops
#define INC     128
#define C1      128                 // heads(4) * hid(32)
#define C2      64
#define HEADS   4
#define NGRAPH  64
#define NCLS    2
#define NCHUNK  ((NN + 255) / 256)  // 391
#define POOL_CHUNK 128
#define G_ROWS  32                  // rows per gemm block (4 warps x 8)
#define XS_STRIDE (G_ROWS + 4)      // 36: multiple of 4 (LDS.128 align), kills STS conflicts

// ---------------- scratch (static __device__, no allocations) ----------------
__device__ int    g_deg[NN];
__device__ int    g_rs[NN + 1];
__device__ int    g_cur[NN];
__device__ int    g_csr[NETOT];
__device__ int    g_csum[512];
__device__ __half g_h1h[NN * C1];
__device__ float  g_as1[NN * HEADS];
__device__ float  g_ad1[NN * HEADS];
__device__ float  g_x2[NN * C1];
__device__ __half g_h2h[NN * C2];
__device__ float  g_as2[NN];
__device__ float  g_ad2[NN];
__device__ float  g_out2[NN * C2];
__device__ float  g_gsum[NGRAPH * C2];
__device__ int    g_gcnt[NGRAPH];

__device__ __forceinline__ float lrelu(float x) { return x > 0.f ? x : 0.2f * x; }
__device__ __forceinline__ float elu1(float x)  { return x > 0.f ? x : expm1f(x); }

// packed f32x2 FMA (FFMA2) — ptxas never emits this from C++
__device__ __forceinline__ void ffma2(unsigned long long& acc,
                                      unsigned long long ab, unsigned long long w) {
    asm("fma.rn.f32x2 %0, %1, %2, %0;" : "+l"(acc) : "l"(ab), "l"(w));
}
__device__ __forceinline__ unsigned long long bcast2(float v) {
    unsigned long long r;
    asm("mov.b64 %0, {%1, %1};" : "=l"(r) : "f"(v));
    return r;
}

// ---------------- CSR build ----------------
__global__ void k_init() {
    int i = blockIdx.x * blockDim.x + threadIdx.x;
    if (i < NN) g_deg[i] = 1;                 // self loop pre-counted
    if (i < NGRAPH * C2) g_gsum[i] = 0.f;
    if (i < NGRAPH) g_gcnt[i] = 0;
}

__global__ void k_hist(const int* __restrict__ dst) {
    int e4 = blockIdx.x * blockDim.x + threadIdx.x;
    if (e4 * 4 + 3 < EE) {
        int4 d = *(const int4*)(dst + e4 * 4);
        atomicAdd(&g_deg[d.x], 1);
        atomicAdd(&g_deg[d.y], 1);
        atomicAdd(&g_deg[d.z], 1);
        atomicAdd(&g_deg[d.w], 1);
    } else {
        for (int e = e4 * 4; e < EE; e++) atomicAdd(&g_deg[dst[e]], 1);
    }
}

__global__ void k_scanA() {
    __shared__ int sh[256];
    int i = blockIdx.x * 256 + threadIdx.x;
    int v = (i < NN) ? g_deg[i] : 0;
    sh[threadIdx.x] = v;
    __syncthreads();
    #pragma unroll
    for (int off = 1; off < 256; off <<= 1) {
        int t = (threadIdx.x >= off) ? sh[threadIdx.x - off] : 0;
        __syncthreads();
        sh[threadIdx.x] += t;
        __syncthreads();
    }
    if (i < NN) g_rs[i] = sh[threadIdx.x] - v;     // chunk-local exclusive
    if (threadIdx.x == 255) g_csum[blockIdx.x] = sh[255];
}

__global__ void k_scanB(int nchunk) {
    __shared__ int sh[512];
    int t = threadIdx.x;
    int v = (t < nchunk) ? g_csum[t] : 0;
    sh[t] = v;
    __syncthreads();
    #pragma unroll
    for (int off = 1; off < 512; off <<= 1) {
        int tv = (t >= off) ? sh[t - off] : 0;
        __syncthreads();
        sh[t] += tv;
        __syncthreads();
    }
    if (t < nchunk) g_csum[t] = sh[t] - v;         // exclusive
}

__global__ void k_scanC() {
    int i = blockIdx.x * 256 + threadIdx.x;
    if (i < NN) {
        int r = g_rs[i] + g_csum[blockIdx.x];
        g_rs[i] = r;
        g_cur[i] = r;
    }
    if (i == 0) g_rs[NN] = NETOT;
}

__global__ void k_scatter(const int* __restrict__ ei) {
    int idx = blockIdx.x * blockDim.x + threadIdx.x;
    if (idx >= NETOT) return;
    int s, d;
    if (idx < EE) { s = ei[idx]; d = ei[EE + idx]; }
    else          { s = idx - EE; d = s; }
    int pos = atomicAdd(&g_cur[d], 1);
    g_csr[pos] = s;
}

// ---------------- GEMM1: h1 = x @ W1 (fp16 out) + attention scalars ----------------
// block: 128 threads = 4 warps; 32 rows/block; warp w -> rows 8w..8w+7,
// thread lane -> cols 4*lane..4*lane+3. xs transposed [k][row], broadcast LDS.128.
__global__ void __launch_bounds__(128) k_gemm1(
        const float* __restrict__ x, const float* __restrict__ W1,
        const float* __restrict__ att_s, const float* __restrict__ att_d) {
    __shared__ __align__(16) float xs[INC][XS_STRIDE];
    int t = threadIdx.x;
    int w = t >> 5, lane = t & 31;
    int row0 = blockIdx.x * G_ROWS;               // 100000/32 = 3125 exact

    // prologue: transpose 32x128 tile into xs[k][r]; conflict-free STS
    {
        int r = t & 31;
        int kc = (t >> 5) * 32;
        const float* xr = x + (row0 + r) * INC + kc;
        #pragma unroll
        for (int i = 0; i < 8; i++) {
            float4 v = *(const float4*)(xr + 4 * i);
            xs[kc + 4 * i + 0][r] = v.x;
            xs[kc + 4 * i + 1][r] = v.y;
            xs[kc + 4 * i + 2][r] = v.z;
            xs[kc + 4 * i + 3][r] = v.w;
        }
    }
    __syncthreads();

    int rbase = 8 * w;
    unsigned long long acc[4][4];                  // [row-pair][col]
    #pragma unroll
    for (int p = 0; p < 4; p++)
        #pragma unroll
        for (int c = 0; c < 4; c++) acc[p][c] = 0ull;

    #pragma unroll 8
    for (int k = 0; k < INC; k++) {
        float4 wv = *(const float4*)(W1 + k * C1 + 4 * lane);
        unsigned long long wb0 = bcast2(wv.x), wb1 = bcast2(wv.y);
        unsigned long long wb2 = bcast2(wv.z), wb3 = bcast2(wv.w);
        #pragma unroll
        for (int j = 0; j < 2; j++) {
            float4 xv = *(const float4*)&xs[k][rbase + 4 * j];   // broadcast
            unsigned long long p0 = *(unsigned long long*)&xv.x;
            unsigned long long p1 = *(unsigned long long*)&xv.z;
            ffma2(acc[2*j  ][0], p0, wb0); ffma2(acc[2*j  ][1], p0, wb1);
            ffma2(acc[2*j  ][2], p0, wb2); ffma2(acc[2*j  ][3], p0, wb3);
            ffma2(acc[2*j+1][0], p1, wb0); ffma2(acc[2*j+1][1], p1, wb1);
            ffma2(acc[2*j+1][2], p1, wb2); ffma2(acc[2*j+1][3], p1, wb3);
        }
    }

    int head = lane >> 3;                          // cols [32*head, 32*head+32)
    float4 asv = *(const float4*)(att_s + 4 * lane);
    float4 adv = *(const float4*)(att_d + 4 * lane);
    #pragma unroll
    for (int p = 0; p < 4; p++) {
        #pragma unroll
        for (int h = 0; h < 2; h++) {              // two rows in the pair
            int row = row0 + rbase + 2 * p + h;
            float v0 = ((float*)&acc[p][0])[h];
            float v1 = ((float*)&acc[p][1])[h];
            float v2 = ((float*)&acc[p][2])[h];
            float v3 = ((float*)&acc[p][3])[h];
            __half2 h01 = __floats2half2_rn(v0, v1);
            __half2 h23 = __floats2half2_rn(v2, v3);
            uint2 hh = make_uint2(*(unsigned*)&h01, *(unsigned*)&h23);
            *(uint2*)(g_h1h + row * C1 + 4 * lane) = hh;
            float s = v0 * asv.x + v1 * asv.y + v2 * asv.z + v3 * asv.w;
            float d = v0 * adv.x + v1 * adv.y + v2 * adv.z + v3 * adv.w;
            #pragma unroll
            for (int o = 4; o; o >>= 1) {          // reduce within 8-lane head group
                s += __shfl_xor_sync(0xffffffffu, s, o);
                d += __shfl_xor_sync(0xffffffffu, d, o);
            }
            if ((lane & 7) == 0) {
                g_as1[row * 4 + head] = s;
                g_ad1[row * 4 + head] = d;
            }
        }
    }
}

// ---------------- conv1 aggregation: one warp per dst node, single pass ----------------
__global__ void k_agg1(const float* __restrict__ b1) {
    int gw = (blockIdx.x * blockDim.x + threadIdx.x) >> 5;
    if (gw >= NN) return;
    int lane = threadIdx.x & 31;
    int beg = g_rs[gw], end = g_rs[gw + 1];
    int head = lane >> 3;                 // lane covers cols [4*lane, 4*lane+4)
    float adh = g_ad1[gw * 4 + head];

    float sum = 0.f;
    float4 acc = make_float4(0.f, 0.f, 0.f, 0.f);
    int j = beg;
    for (; j + 4 <= end; j += 4) {
        int s0 = g_csr[j],     s1 = g_csr[j + 1];
        int s2 = g_csr[j + 2], s3 = g_csr[j + 3];
        float a0 = g_as1[s0 * 4 + head];
        float a1 = g_as1[s1 * 4 + head];
        float a2 = g_as1[s2 * 4 + head];
        float a3 = g_as1[s3 * 4 + head];
        uint2 u0 = *(const uint2*)(g_h1h + s0 * C1 + lane * 4);
        uint2 u1 = *(const uint2*)(g_h1h + s1 * C1 + lane * 4);
        uint2 u2 = *(const uint2*)(g_h1h + s2 * C1 + lane * 4);
        uint2 u3 = *(const uint2*)(g_h1h + s3 * C1 + lane * 4);
        float e0 = __expf(lrelu(a0 + adh));
        float e1 = __expf(lrelu(a1 + adh));
        float e2 = __expf(lrelu(a2 + adh));
        float e3 = __expf(lrelu(a3 + adh));
        sum += (e0 + e1) + (e2 + e3);
        float2 f0a = __half22float2(*(__half2*)&u0.x), f0b = __half22float2(*(__half2*)&u0.y);
        float2 f1a = __half22float2(*(__half2*)&u1.x), f1b = __half22float2(*(__half2*)&u1.y);
        float2 f2a = __half22float2(*(__half2*)&u2.x), f2b = __half22float2(*(__half2*)&u2.y);
        float2 f3a = __half22float2(*(__half2*)&u3.x), f3b = __half22float2(*(__half2*)&u3.y);
        acc.x += e0 * f0a.x + e1 * f1a.x + e2 * f2a.x + e3 * f3a.x;
        acc.y += e0 * f0a.y + e1 * f1a.y + e2 * f2a.y + e3 * f3a.y;
        acc.z += e0 * f0b.x + e1 * f1b.x + e2 * f2b.x + e3 * f3b.x;
        acc.w += e0 * f0b.y + e1 * f1b.y + e2 * f2b.y + e3 * f3b.y;
    }
    for (; j < end; j++) {
        int s = g_csr[j];
        float e = __expf(lrelu(g_as1[s * 4 + head] + adh));
        sum += e;
        uint2 u = *(const uint2*)(g_h1h + s * C1 + lane * 4);
        float2 fa = __half22float2(*(__half2*)&u.x);
        float2 fb = __half22float2(*(__half2*)&u.y);
        acc.x += e * fa.x; acc.y += e * fa.y;
        acc.z += e * fb.x; acc.w += e * fb.y;
    }
    float inv = 1.0f / (sum + 1e-16f);
    float4 bv = *(const float4*)(b1 + lane * 4);
    float4 o;
    o.x = elu1(acc.x * inv + bv.x);
    o.y = elu1(acc.y * inv + bv.y);
    o.z = elu1(acc.z * inv + bv.z);
    o.w = elu1(acc.w * inv + bv.w);
    *(float4*)(g_x2 + gw * C1 + lane * 4) = o;
}

// ---------------- GEMM2: h2 = x2 @ W2 (fp16 out) + attention scalars ----------------
// block: 128 threads = 4 warps; 32 rows/block; warp w -> rows 8w..8w+7,
// thread lane -> cols 2*lane, 2*lane+1.
__global__ void __launch_bounds__(128) k_gemm2(
        const float* __restrict__ W2,
        const float* __restrict__ att_s, const float* __restrict__ att_d) {
    __shared__ __align__(16) float xs[C1][XS_STRIDE];
    int t = threadIdx.x;
    int w = t >> 5, lane = t & 31;
    int row0 = blockIdx.x * G_ROWS;               // 3125 blocks exact

    {
        int r = t & 31;
        int kc = (t >> 5) * 32;
        const float* xr = g_x2 + (row0 + r) * C1 + kc;
        #pragma unroll
        for (int i = 0; i < 8; i++) {
            float4 v = *(const float4*)(xr + 4 * i);
            xs[kc + 4 * i + 0][r] = v.x;
            xs[kc + 4 * i + 1][r] = v.y;
            xs[kc + 4 * i + 2][r] = v.z;
            xs[kc + 4 * i + 3][r] = v.w;
        }
    }
    __syncthreads();

    int rbase = 8 * w;
    unsigned long long acc[4][2];
    #pragma unroll
    for (int p = 0; p < 4; p++) { acc[p][0] = 0ull; acc[p][1] = 0ull; }

    #pragma unroll 8
    for (int k = 0; k < C1; k++) {
        float2 wv = *(const float2*)(W2 + k * C2 + 2 * lane);
        unsigned long long wb0 = bcast2(wv.x), wb1 = bcast2(wv.y);
        #pragma unroll
        for (int j = 0; j < 2; j++) {
            float4 xv = *(const float4*)&xs[k][rbase + 4 * j];   // broadcast
            unsigned long long p0 = *(unsigned long long*)&xv.x;
            unsigned long long p1 = *(unsigned long long*)&xv.z;
            ffma2(acc[2*j  ][0], p0, wb0); ffma2(acc[2*j  ][1], p0, wb1);
            ffma2(acc[2*j+1][0], p1, wb0); ffma2(acc[2*j+1][1], p1, wb1);
        }
    }

    float as0 = att_s[2 * lane], as1 = att_s[2 * lane + 1];
    float ad0 = att_d[2 * lane], ad1 = att_d[2 * lane + 1];
    #pragma unroll
    for (int p = 0; p < 4; p++) {
        #pragma unroll
        for (int h = 0; h < 2; h++) {
            int row = row0 + rbase + 2 * p + h;
            float v0 = ((float*)&acc[p][0])[h];
            float v1 = ((float*)&acc[p][1])[h];
            __half2 hv = __floats2half2_rn(v0, v1);
            *(unsigned*)(g_h2h + row * C2 + 2 * lane) = *(unsigned*)&hv;
            float s = v0 * as0 + v1 * as1;
            float d = v0 * ad0 + v1 * ad1;
            #pragma unroll
            for (int o = 16; o; o >>= 1) {
                s += __shfl_xor_sync(0xffffffffu, s, o);
                d += __shfl_xor_sync(0xffffffffu, d, o);
            }
            if (lane == 0) { g_as2[row] = s; g_ad2[row] = d; }
        }
    }
}

// ---------------- conv2 aggregation: one warp per node, single pass ----------------
__global__ void k_agg2(const float* __restrict__ b2) {
    int gw = (blockIdx.x * blockDim.x + threadIdx.x) >> 5;
    if (gw >= NN) return;
    int lane = threadIdx.x & 31;
    int beg = g_rs[gw], end = g_rs[gw + 1];
    float ad = g_ad2[gw];

    float sum = 0.f;
    float2 acc = make_float2(0.f, 0.f);
    int j = beg;
    for (; j + 4 <= end; j += 4) {
        int s0 = g_csr[j],     s1 = g_csr[j + 1];
        int s2 = g_csr[j + 2], s3 = g_csr[j + 3];
        float a0 = g_as2[s0], a1 = g_as2[s1];
        float a2 = g_as2[s2], a3 = g_as2[s3];
        __half2 u0 = *(const __half2*)(g_h2h + s0 * C2 + lane * 2);
        __half2 u1 = *(const __half2*)(g_h2h + s1 * C2 + lane * 2);
        __half2 u2 = *(const __half2*)(g_h2h + s2 * C2 + lane * 2);
        __half2 u3 = *(const __half2*)(g_h2h + s3 * C2 + lane * 2);
        float e0 = __expf(lrelu(a0 + ad));
        float e1 = __expf(lrelu(a1 + ad));
        float e2 = __expf(lrelu(a2 + ad));
        float e3 = __expf(lrelu(a3 + ad));
        sum += (e0 + e1) + (e2 + e3);
        float2 f0 = __half22float2(u0), f1 = __half22float2(u1);
        float2 f2 = __half22float2(u2), f3 = __half22float2(u3);
        acc.x += e0 * f0.x + e1 * f1.x + e2 * f2.x + e3 * f3.x;
        acc.y += e0 * f0.y + e1 * f1.y + e2 * f2.y + e3 * f3.y;
    }
    for (; j < end; j++) {
        int s = g_csr[j];
        float e = __expf(lrelu(g_as2[s] + ad));
        sum += e;
        float2 f = __half22float2(*(const __half2*)(g_h2h + s * C2 + lane * 2));
        acc.x += e * f.x; acc.y += e * f.y;
    }
    float inv = 1.0f / (sum + 1e-16f);
    float2 bv = *(const float2*)(b2 + lane * 2);
    float2 o;
    o.x = elu1(acc.x * inv + bv.x);
    o.y = elu1(acc.y * inv + bv.y);
    *(float2*)(g_out2 + gw * C2 + lane * 2) = o;
}

// ---------------- global mean pool (batch sorted) ----------------
__global__ void k_pool(const int* __restrict__ batch) {
    int t = threadIdx.x;  // 64 threads = 64 channels
    int n0 = blockIdx.x * POOL_CHUNK;
    if (n0 >= NN) return;
    int n1 = n0 + POOL_CHUNK; if (n1 > NN) n1 = NN;
    float acc = 0.f;
    int cnt = 0;
    int g = batch[n0];
    for (int n = n0; n < n1; n++) {
        int gn = batch[n];
        if (gn != g) {
            atomicAdd(&g_gsum[g * C2 + t], acc);
            if (t == 0) atomicAdd(&g_gcnt[g], cnt);
            acc = 0.f; cnt = 0; g = gn;
        }
        acc += g_out2[n * C2 + t];
        cnt++;
    }
    atomicAdd(&g_gsum[g * C2 + t], acc);
    if (t == 0) atomicAdd(&g_gcnt[g], cnt);
}

// ---------------- classifier ----------------
__global__ void k_final(const float* __restrict__ Wc, const float* __restrict__ bc,
                        float* __restrict__ out) {
    int t = threadIdx.x;
    if (t >= NGRAPH * NCLS) return;
    int gph = t >> 1, k = t & 1;
    float cnt = (float)g_gcnt[gph];
    if (cnt < 1.f) cnt = 1.f;
    float s = 0.f;
    #pragma unroll
    for (int c = 0; c < C2; c++) s += g_gsum[gph * C2 + c] * Wc[c * NCLS + k];
    out[t] = s / cnt + bc[k];
}

// ---------------- launch ----------------
extern "C" void kernel_launch(void* const* d_in, const int* in_sizes, int n_in,
                              void* d_out, int out_size) {
    const float* x     = (const float*)d_in[0];
    const int*   ei    = (const int*)  d_in[1];   // [2, E] row-major
    const int*   batch = (const int*)  d_in[2];
    const float* W1    = (const float*)d_in[3];
    const float* atts1 = (const float*)d_in[4];
    const float* attd1 = (const float*)d_in[5];
    const float* b1    = (const float*)d_in[6];
    const float* W2    = (const float*)d_in[7];
    const float* atts2 = (const float*)d_in[8];
    const float* attd2 = (const float*)d_in[9];
    const float* b2    = (const float*)d_in[10];
    const float* Wc    = (const float*)d_in[11];
    const float* bc    = (const float*)d_in[12];
    float* out = (float*)d_out;

    // order keeps gemm1 at the launch index ncu captures
    k_init   <<<(NN + 255) / 256, 256>>>();
    k_hist   <<<(EE / 4 + 255) / 256, 256>>>(ei + EE);
    k_scanA  <<<NCHUNK, 256>>>();
    k_gemm1  <<<NN / G_ROWS, 128>>>(x, W1, atts1, attd1);
    k_scanB  <<<1, 512>>>(NCHUNK);
    k_scanC  <<<NCHUNK, 256>>>();
    k_scatter<<<(NETOT + 255) / 256, 256>>>(ei);

    k_agg1   <<<(NN * 32 + 255) / 256, 256>>>(b1);
    k_gemm2  <<<NN / G_ROWS, 128>>>(W2, atts2, attd2);
    k_agg2   <<<(NN * 32 + 255) / 256, 256>>>(b2);

    k_pool   <<<(NN + POOL_CHUNK - 1) / POOL_CHUNK, 64>>>(batch);
    k_final  <<<1, 128>>>(Wc, bc, out);
}

// round 5
// speedup vs baseline: 2.0587x; 1.3509x over previous
#include <cuda_runtime.h>
#include <cuda_fp16.h>
#include <math.h>
#include <stdint.h>

#define NN      100000
#define EE      1600000
#define NETOT   (EE + NN)           // edges + self loops
#define INC     128
#define C1      128                 // heads(4) * hid(32)
#define C2      64
#define HEADS   4
#define NGRAPH  64
#define NCLS    2
#define NCHUNK  ((NN + 255) / 256)  // 391
#define POOL_CHUNK 128
#define MB      64                  // gemm rows per block

// ---------------- scratch (static __device__, no allocations) ----------------
__device__ int    g_deg[NN];
__device__ int    g_rs[NN + 1];
__device__ int    g_cur[NN];
__device__ int    g_csr[NETOT];
__device__ int    g_csum[512];
__device__ __align__(16) __half g_h1h[NN * C1];
__device__ float  g_as1[NN * HEADS];
__device__ float  g_ad1[NN * HEADS];
__device__ __align__(16) __half g_x2h[NN * C1];
__device__ __align__(16) __half g_h2h[NN * C2];
__device__ float  g_as2[NN];
__device__ float  g_ad2[NN];
__device__ float  g_out2[NN * C2];
__device__ float  g_gsum[NGRAPH * C2];
__device__ int    g_gcnt[NGRAPH];
__device__ __align__(16) __half g_w1t[C1 * INC];   // W1^T fp16, ldsm-swizzled
__device__ __align__(16) __half g_w2t[C2 * C1];    // W2^T fp16, ldsm-swizzled

__device__ __forceinline__ float lrelu(float x) { return x > 0.f ? x : 0.2f * x; }
__device__ __forceinline__ float elu1(float x)  { return x > 0.f ? x : expm1f(x); }

__device__ __forceinline__ void ldsm4(uint32_t& r0, uint32_t& r1, uint32_t& r2, uint32_t& r3,
                                      uint32_t addr) {
    asm volatile("ldmatrix.sync.aligned.m8n8.x4.shared.b16 {%0,%1,%2,%3}, [%4];"
                 : "=r"(r0), "=r"(r1), "=r"(r2), "=r"(r3) : "r"(addr));
}
__device__ __forceinline__ void mma16816(float* c, const uint32_t* a, uint32_t b0, uint32_t b1) {
    asm volatile("mma.sync.aligned.m16n8k16.row.col.f32.f16.f16.f32 "
                 "{%0,%1,%2,%3},{%4,%5,%6,%7},{%8,%9},{%0,%1,%2,%3};"
                 : "+f"(c[0]), "+f"(c[1]), "+f"(c[2]), "+f"(c[3])
                 : "r"(a[0]), "r"(a[1]), "r"(a[2]), "r"(a[3]), "r"(b0), "r"(b1));
}

// ---------------- CSR build ----------------
__global__ void k_init() {
    int i = blockIdx.x * blockDim.x + threadIdx.x;
    if (i < NN) g_deg[i] = 1;                 // self loop pre-counted
    if (i < NGRAPH * C2) g_gsum[i] = 0.f;
    if (i < NGRAPH) g_gcnt[i] = 0;
}

__global__ void k_hist(const int* __restrict__ dst) {
    int e4 = blockIdx.x * blockDim.x + threadIdx.x;
    if (e4 * 4 + 3 < EE) {
        int4 d = *(const int4*)(dst + e4 * 4);
        atomicAdd(&g_deg[d.x], 1);
        atomicAdd(&g_deg[d.y], 1);
        atomicAdd(&g_deg[d.z], 1);
        atomicAdd(&g_deg[d.w], 1);
    } else {
        for (int e = e4 * 4; e < EE; e++) atomicAdd(&g_deg[dst[e]], 1);
    }
}

// one-time weight transpose + fp16 + ldsm swizzle bake
__global__ void k_prepW(const float* __restrict__ W1, const float* __restrict__ W2) {
    int idx = blockIdx.x * blockDim.x + threadIdx.x;
    if (idx < 128 * 16) {
        int n = idx >> 4, kc = idx & 15;
        int sc = kc ^ (n & 7);
        #pragma unroll
        for (int j = 0; j < 8; j++)
            g_w1t[n * 128 + (sc << 3) + j] = __float2half(W1[(kc * 8 + j) * C1 + n]);
    } else if (idx < 128 * 16 + 64 * 16) {
        int q = idx - 128 * 16;
        int n = q >> 4, kc = q & 15;
        int sc = kc ^ (n & 7);
        #pragma unroll
        for (int j = 0; j < 8; j++)
            g_w2t[n * 128 + (sc << 3) + j] = __float2half(W2[(kc * 8 + j) * C2 + n]);
    }
}

__global__ void k_scanA() {
    __shared__ int sh[256];
    int i = blockIdx.x * 256 + threadIdx.x;
    int v = (i < NN) ? g_deg[i] : 0;
    sh[threadIdx.x] = v;
    __syncthreads();
    #pragma unroll
    for (int off = 1; off < 256; off <<= 1) {
        int t = (threadIdx.x >= off) ? sh[threadIdx.x - off] : 0;
        __syncthreads();
        sh[threadIdx.x] += t;
        __syncthreads();
    }
    if (i < NN) g_rs[i] = sh[threadIdx.x] - v;     // chunk-local exclusive
    if (threadIdx.x == 255) g_csum[blockIdx.x] = sh[255];
}

__global__ void k_scanB(int nchunk) {
    __shared__ int sh[512];
    int t = threadIdx.x;
    int v = (t < nchunk) ? g_csum[t] : 0;
    sh[t] = v;
    __syncthreads();
    #pragma unroll
    for (int off = 1; off < 512; off <<= 1) {
        int tv = (t >= off) ? sh[t - off] : 0;
        __syncthreads();
        sh[t] += tv;
        __syncthreads();
    }
    if (t < nchunk) g_csum[t] = sh[t] - v;         // exclusive
}

__global__ void k_scanC() {
    int i = blockIdx.x * 256 + threadIdx.x;
    if (i < NN) {
        int r = g_rs[i] + g_csum[blockIdx.x];
        g_rs[i] = r;
        g_cur[i] = r;
    }
    if (i == 0) g_rs[NN] = NETOT;
}

__global__ void k_scatter(const int* __restrict__ ei) {
    int idx = blockIdx.x * blockDim.x + threadIdx.x;
    if (idx >= NETOT) return;
    int s, d;
    if (idx < EE) { s = ei[idx]; d = ei[EE + idx]; }
    else          { s = idx - EE; d = s; }
    int pos = atomicAdd(&g_cur[d], 1);
    g_csr[pos] = s;
}

// ---------------- GEMM1 (HMMA): h1 = x @ W1, fp16 out + attention scalars ----------------
// 256 threads = 8 warps, 64 rows/block. Warp grid 2(M) x 4(N); warp = M32 x N32; N-warp == head.
__global__ void __launch_bounds__(256) k_gemm1(
        const float* __restrict__ x,
        const float* __restrict__ att_s, const float* __restrict__ att_d) {
    __shared__ __align__(16) __half xs[MB * 128];     // 16KB, swizzled [m][k]
    __shared__ __align__(16) __half ws[128 * 128];    // 32KB, swizzled [n][k]
    int tid = threadIdx.x;
    int row0 = blockIdx.x * MB;

    // copy pre-swizzled W1^T: 2048 uint4 / 256 thr
    {
        const uint4* wsrc = (const uint4*)g_w1t;
        uint4* wdst = (uint4*)ws;
        #pragma unroll
        for (int i = 0; i < 8; i++) wdst[tid + 256 * i] = wsrc[tid + 256 * i];
    }
    // x tile: 64 rows x 16 chunks of 8 halves; 1024 chunks / 256 thr
    #pragma unroll
    for (int i = 0; i < 4; i++) {
        int idx = tid + 256 * i;
        int m = idx >> 4, c = idx & 15;
        int gm = row0 + m; if (gm > NN - 1) gm = NN - 1;
        const float4* xp = (const float4*)(x + gm * INC + c * 8);
        float4 v0 = xp[0], v1 = xp[1];
        __half2 h0 = __floats2half2_rn(v0.x, v0.y);
        __half2 h1 = __floats2half2_rn(v0.z, v0.w);
        __half2 h2 = __floats2half2_rn(v1.x, v1.y);
        __half2 h3 = __floats2half2_rn(v1.z, v1.w);
        uint4 pk = make_uint4(*(unsigned*)&h0, *(unsigned*)&h1, *(unsigned*)&h2, *(unsigned*)&h3);
        int sc = c ^ (m & 7);
        *(uint4*)(xs + m * 128 + sc * 8) = pk;
    }
    __syncthreads();

    int w = tid >> 5, lane = tid & 31;
    int mw = w >> 2, nw = w & 3;
    int i8 = lane >> 3, r8 = lane & 7;
    uint32_t xbase = (uint32_t)__cvta_generic_to_shared(xs);
    uint32_t wbase = (uint32_t)__cvta_generic_to_shared(ws);

    // ldsm row indices (constant across kt)
    int rowA[2], rowB[2];
    #pragma unroll
    for (int mt = 0; mt < 2; mt++) rowA[mt] = mw * 32 + mt * 16 + (i8 & 1) * 8 + r8;
    #pragma unroll
    for (int p = 0; p < 2; p++)   rowB[p] = nw * 32 + p * 16 + (i8 >> 1) * 8 + r8;
    int kcA_off = (i8 >> 1);   // +0/+1 chunk within k16
    int kcB_off = (i8 & 1);

    float c[2][4][4];
    #pragma unroll
    for (int mt = 0; mt < 2; mt++)
        #pragma unroll
        for (int nt = 0; nt < 4; nt++)
            #pragma unroll
            for (int q = 0; q < 4; q++) c[mt][nt][q] = 0.f;

    #pragma unroll
    for (int kt = 0; kt < 8; kt++) {
        uint32_t A[2][4], B[2][4];
        #pragma unroll
        for (int mt = 0; mt < 2; mt++) {
            int kc = kt * 2 + kcA_off;
            uint32_t addr = xbase + rowA[mt] * 256 + (((kc ^ (rowA[mt] & 7))) << 4);
            ldsm4(A[mt][0], A[mt][1], A[mt][2], A[mt][3], addr);
        }
        #pragma unroll
        for (int p = 0; p < 2; p++) {
            int kc = kt * 2 + kcB_off;
            uint32_t addr = wbase + rowB[p] * 256 + (((kc ^ (rowB[p] & 7))) << 4);
            ldsm4(B[p][0], B[p][1], B[p][2], B[p][3], addr);
        }
        #pragma unroll
        for (int mt = 0; mt < 2; mt++) {
            mma16816(c[mt][0], A[mt], B[0][0], B[0][1]);
            mma16816(c[mt][1], A[mt], B[0][2], B[0][3]);
            mma16816(c[mt][2], A[mt], B[1][0], B[1][1]);
            mma16816(c[mt][3], A[mt], B[1][2], B[1][3]);
        }
    }

    // epilogue: store h1 fp16, per-row att dot (intra-warp: N-warp == head)
    int quad = lane & 3;
    #pragma unroll
    for (int mt = 0; mt < 2; mt++) {
        int rlo = row0 + mw * 32 + mt * 16 + (lane >> 2);
        int rhi = rlo + 8;
        float slo = 0.f, shi = 0.f, dlo = 0.f, dhi = 0.f;
        #pragma unroll
        for (int nt = 0; nt < 4; nt++) {
            int cb = nw * 32 + nt * 8 + 2 * quad;
            float as0 = att_s[cb], as1 = att_s[cb + 1];
            float ad0 = att_d[cb], ad1 = att_d[cb + 1];
            float v0 = c[mt][nt][0], v1 = c[mt][nt][1];
            float v2 = c[mt][nt][2], v3 = c[mt][nt][3];
            slo += v0 * as0 + v1 * as1;  dlo += v0 * ad0 + v1 * ad1;
            shi += v2 * as0 + v3 * as1;  dhi += v2 * ad0 + v3 * ad1;
            if (rlo < NN) {
                __half2 h = __floats2half2_rn(v0, v1);
                *(unsigned*)(g_h1h + rlo * C1 + cb) = *(unsigned*)&h;
            }
            if (rhi < NN) {
                __half2 h = __floats2half2_rn(v2, v3);
                *(unsigned*)(g_h1h + rhi * C1 + cb) = *(unsigned*)&h;
            }
        }
        #pragma unroll
        for (int o = 1; o <= 2; o <<= 1) {
            slo += __shfl_xor_sync(0xffffffffu, slo, o);
            shi += __shfl_xor_sync(0xffffffffu, shi, o);
            dlo += __shfl_xor_sync(0xffffffffu, dlo, o);
            dhi += __shfl_xor_sync(0xffffffffu, dhi, o);
        }
        if (quad == 0) {
            if (rlo < NN) { g_as1[rlo * 4 + nw] = slo; g_ad1[rlo * 4 + nw] = dlo; }
            if (rhi < NN) { g_as1[rhi * 4 + nw] = shi; g_ad1[rhi * 4 + nw] = dhi; }
        }
    }
}

// ---------------- conv1 aggregation: one warp per dst node, single pass ----------------
__global__ void k_agg1(const float* __restrict__ b1) {
    int gw = (blockIdx.x * blockDim.x + threadIdx.x) >> 5;
    if (gw >= NN) return;
    int lane = threadIdx.x & 31;
    int beg = g_rs[gw], end = g_rs[gw + 1];
    int head = lane >> 3;                 // lane covers cols [4*lane, 4*lane+4)
    float adh = g_ad1[gw * 4 + head];

    float sum = 0.f;
    float4 acc = make_float4(0.f, 0.f, 0.f, 0.f);
    int j = beg;
    for (; j + 4 <= end; j += 4) {
        int s0 = g_csr[j],     s1 = g_csr[j + 1];
        int s2 = g_csr[j + 2], s3 = g_csr[j + 3];
        float a0 = g_as1[s0 * 4 + head];
        float a1 = g_as1[s1 * 4 + head];
        float a2 = g_as1[s2 * 4 + head];
        float a3 = g_as1[s3 * 4 + head];
        uint2 u0 = *(const uint2*)(g_h1h + s0 * C1 + lane * 4);
        uint2 u1 = *(const uint2*)(g_h1h + s1 * C1 + lane * 4);
        uint2 u2 = *(const uint2*)(g_h1h + s2 * C1 + lane * 4);
        uint2 u3 = *(const uint2*)(g_h1h + s3 * C1 + lane * 4);
        float e0 = __expf(lrelu(a0 + adh));
        float e1 = __expf(lrelu(a1 + adh));
        float e2 = __expf(lrelu(a2 + adh));
        float e3 = __expf(lrelu(a3 + adh));
        sum += (e0 + e1) + (e2 + e3);
        float2 f0a = __half22float2(*(__half2*)&u0.x), f0b = __half22float2(*(__half2*)&u0.y);
        float2 f1a = __half22float2(*(__half2*)&u1.x), f1b = __half22float2(*(__half2*)&u1.y);
        float2 f2a = __half22float2(*(__half2*)&u2.x), f2b = __half22float2(*(__half2*)&u2.y);
        float2 f3a = __half22float2(*(__half2*)&u3.x), f3b = __half22float2(*(__half2*)&u3.y);
        acc.x += e0 * f0a.x + e1 * f1a.x + e2 * f2a.x + e3 * f3a.x;
        acc.y += e0 * f0a.y + e1 * f1a.y + e2 * f2a.y + e3 * f3a.y;
        acc.z += e0 * f0b.x + e1 * f1b.x + e2 * f2b.x + e3 * f3b.x;
        acc.w += e0 * f0b.y + e1 * f1b.y + e2 * f2b.y + e3 * f3b.y;
    }
    for (; j < end; j++) {
        int s = g_csr[j];
        float e = __expf(lrelu(g_as1[s * 4 + head] + adh));
        sum += e;
        uint2 u = *(const uint2*)(g_h1h + s * C1 + lane * 4);
        float2 fa = __half22float2(*(__half2*)&u.x);
        float2 fb = __half22float2(*(__half2*)&u.y);
        acc.x += e * fa.x; acc.y += e * fa.y;
        acc.z += e * fb.x; acc.w += e * fb.y;
    }
    float inv = 1.0f / (sum + 1e-16f);
    float4 bv = *(const float4*)(b1 + lane * 4);
    __half2 p0 = __floats2half2_rn(elu1(acc.x * inv + bv.x), elu1(acc.y * inv + bv.y));
    __half2 p1 = __floats2half2_rn(elu1(acc.z * inv + bv.z), elu1(acc.w * inv + bv.w));
    *(uint2*)(g_x2h + gw * C1 + lane * 4) = make_uint2(*(unsigned*)&p0, *(unsigned*)&p1);
}

// ---------------- GEMM2 (HMMA): h2 = x2 @ W2, fp16 out + attention scalars ----------------
// 128 threads = 4 warps, 64 rows/block. Warp grid 2(M) x 2(N); warp = M32 x N32.
__global__ void __launch_bounds__(128) k_gemm2(
        const float* __restrict__ att_s, const float* __restrict__ att_d) {
    __shared__ __align__(16) __half xs[MB * 128];    // 16KB
    __shared__ __align__(16) __half ws[C2 * 128];    // 16KB
    __shared__ float s_part[2][MB], d_part[2][MB];
    int tid = threadIdx.x;
    int row0 = blockIdx.x * MB;

    {
        const uint4* wsrc = (const uint4*)g_w2t;
        uint4* wdst = (uint4*)ws;
        #pragma unroll
        for (int i = 0; i < 8; i++) wdst[tid + 128 * i] = wsrc[tid + 128 * i];
    }
    #pragma unroll
    for (int i = 0; i < 8; i++) {
        int idx = tid + 128 * i;
        int m = idx >> 4, c = idx & 15;
        int gm = row0 + m; if (gm > NN - 1) gm = NN - 1;
        uint4 pk = *(const uint4*)(g_x2h + gm * C1 + c * 8);
        int sc = c ^ (m & 7);
        *(uint4*)(xs + m * 128 + sc * 8) = pk;
    }
    __syncthreads();

    int w = tid >> 5, lane = tid & 31;
    int mw = w >> 1, nw = w & 1;
    int i8 = lane >> 3, r8 = lane & 7;
    uint32_t xbase = (uint32_t)__cvta_generic_to_shared(xs);
    uint32_t wbase = (uint32_t)__cvta_generic_to_shared(ws);

    int rowA[2], rowB[2];
    #pragma unroll
    for (int mt = 0; mt < 2; mt++) rowA[mt] = mw * 32 + mt * 16 + (i8 & 1) * 8 + r8;
    #pragma unroll
    for (int p = 0; p < 2; p++)   rowB[p] = nw * 32 + p * 16 + (i8 >> 1) * 8 + r8;
    int kcA_off = (i8 >> 1), kcB_off = (i8 & 1);

    float c[2][4][4];
    #pragma unroll
    for (int mt = 0; mt < 2; mt++)
        #pragma unroll
        for (int nt = 0; nt < 4; nt++)
            #pragma unroll
            for (int q = 0; q < 4; q++) c[mt][nt][q] = 0.f;

    #pragma unroll
    for (int kt = 0; kt < 8; kt++) {
        uint32_t A[2][4], B[2][4];
        #pragma unroll
        for (int mt = 0; mt < 2; mt++) {
            int kc = kt * 2 + kcA_off;
            uint32_t addr = xbase + rowA[mt] * 256 + (((kc ^ (rowA[mt] & 7))) << 4);
            ldsm4(A[mt][0], A[mt][1], A[mt][2], A[mt][3], addr);
        }
        #pragma unroll
        for (int p = 0; p < 2; p++) {
            int kc = kt * 2 + kcB_off;
            uint32_t addr = wbase + rowB[p] * 256 + (((kc ^ (rowB[p] & 7))) << 4);
            ldsm4(B[p][0], B[p][1], B[p][2], B[p][3], addr);
        }
        #pragma unroll
        for (int mt = 0; mt < 2; mt++) {
            mma16816(c[mt][0], A[mt], B[0][0], B[0][1]);
            mma16816(c[mt][1], A[mt], B[0][2], B[0][3]);
            mma16816(c[mt][2], A[mt], B[1][0], B[1][1]);
            mma16816(c[mt][3], A[mt], B[1][2], B[1][3]);
        }
    }

    int quad = lane & 3;
    #pragma unroll
    for (int mt = 0; mt < 2; mt++) {
        int rloc = mw * 32 + mt * 16 + (lane >> 2);   // local row
        int rlo = row0 + rloc, rhi = rlo + 8;
        float slo = 0.f, shi = 0.f, dlo = 0.f, dhi = 0.f;
        #pragma unroll
        for (int nt = 0; nt < 4; nt++) {
            int cb = nw * 32 + nt * 8 + 2 * quad;
            float as0 = att_s[cb], as1 = att_s[cb + 1];
            float ad0 = att_d[cb], ad1 = att_d[cb + 1];
            float v0 = c[mt][nt][0], v1 = c[mt][nt][1];
            float v2 = c[mt][nt][2], v3 = c[mt][nt][3];
            slo += v0 * as0 + v1 * as1;  dlo += v0 * ad0 + v1 * ad1;
            shi += v2 * as0 + v3 * as1;  dhi += v2 * ad0 + v3 * ad1;
            if (rlo < NN) {
                __half2 h = __floats2half2_rn(v0, v1);
                *(unsigned*)(g_h2h + rlo * C2 + cb) = *(unsigned*)&h;
            }
            if (rhi < NN) {
                __half2 h = __floats2half2_rn(v2, v3);
                *(unsigned*)(g_h2h + rhi * C2 + cb) = *(unsigned*)&h;
            }
        }
        #pragma unroll
        for (int o = 1; o <= 2; o <<= 1) {
            slo += __shfl_xor_sync(0xffffffffu, slo, o);
            shi += __shfl_xor_sync(0xffffffffu, shi, o);
            dlo += __shfl_xor_sync(0xffffffffu, dlo, o);
            dhi += __shfl_xor_sync(0xffffffffu, dhi, o);
        }
        if (quad == 0) {
            s_part[nw][rloc]     = slo;  d_part[nw][rloc]     = dlo;
            s_part[nw][rloc + 8] = shi;  d_part[nw][rloc + 8] = dhi;
        }
    }
    __syncthreads();
    if (tid < MB) {
        int row = row0 + tid;
        if (row < NN) {
            g_as2[row] = s_part[0][tid] + s_part[1][tid];
            g_ad2[row] = d_part[0][tid] + d_part[1][tid];
        }
    }
}

// ---------------- conv2 aggregation: one warp per node, single pass ----------------
__global__ void k_agg2(const float* __restrict__ b2) {
    int gw = (blockIdx.x * blockDim.x + threadIdx.x) >> 5;
    if (gw >= NN) return;
    int lane = threadIdx.x & 31;
    int beg = g_rs[gw], end = g_rs[gw + 1];
    float ad = g_ad2[gw];

    float sum = 0.f;
    float2 acc = make_float2(0.f, 0.f);
    int j = beg;
    for (; j + 4 <= end; j += 4) {
        int s0 = g_csr[j],     s1 = g_csr[j + 1];
        int s2 = g_csr[j + 2], s3 = g_csr[j + 3];
        float a0 = g_as2[s0], a1 = g_as2[s1];
        float a2 = g_as2[s2], a3 = g_as2[s3];
        __half2 u0 = *(const __half2*)(g_h2h + s0 * C2 + lane * 2);
        __half2 u1 = *(const __half2*)(g_h2h + s1 * C2 + lane * 2);
        __half2 u2 = *(const __half2*)(g_h2h + s2 * C2 + lane * 2);
        __half2 u3 = *(const __half2*)(g_h2h + s3 * C2 + lane * 2);
        float e0 = __expf(lrelu(a0 + ad));
        float e1 = __expf(lrelu(a1 + ad));
        float e2 = __expf(lrelu(a2 + ad));
        float e3 = __expf(lrelu(a3 + ad));
        sum += (e0 + e1) + (e2 + e3);
        float2 f0 = __half22float2(u0), f1 = __half22float2(u1);
        float2 f2 = __half22float2(u2), f3 = __half22float2(u3);
        acc.x += e0 * f0.x + e1 * f1.x + e2 * f2.x + e3 * f3.x;
        acc.y += e0 * f0.y + e1 * f1.y + e2 * f2.y + e3 * f3.y;
    }
    for (; j < end; j++) {
        int s = g_csr[j];
        float e = __expf(lrelu(g_as2[s] + ad));
        sum += e;
        float2 f = __half22float2(*(const __half2*)(g_h2h + s * C2 + lane * 2));
        acc.x += e * f.x; acc.y += e * f.y;
    }
    float inv = 1.0f / (sum + 1e-16f);
    float2 bv = *(const float2*)(b2 + lane * 2);
    float2 o;
    o.x = elu1(acc.x * inv + bv.x);
    o.y = elu1(acc.y * inv + bv.y);
    *(float2*)(g_out2 + gw * C2 + lane * 2) = o;
}

// ---------------- global mean pool (batch sorted) ----------------
__global__ void k_pool(const int* __restrict__ batch) {
    int t = threadIdx.x;  // 64 threads = 64 channels
    int n0 = blockIdx.x * POOL_CHUNK;
    if (n0 >= NN) return;
    int n1 = n0 + POOL_CHUNK; if (n1 > NN) n1 = NN;
    float acc = 0.f;
    int cnt = 0;
    int g = batch[n0];
    for (int n = n0; n < n1; n++) {
        int gn = batch[n];
        if (gn != g) {
            atomicAdd(&g_gsum[g * C2 + t], acc);
            if (t == 0) atomicAdd(&g_gcnt[g], cnt);
            acc = 0.f; cnt = 0; g = gn;
        }
        acc += g_out2[n * C2 + t];
        cnt++;
    }
    atomicAdd(&g_gsum[g * C2 + t], acc);
    if (t == 0) atomicAdd(&g_gcnt[g], cnt);
}

// ---------------- classifier ----------------
__global__ void k_final(const float* __restrict__ Wc, const float* __restrict__ bc,
                        float* __restrict__ out) {
    int t = threadIdx.x;
    if (t >= NGRAPH * NCLS) return;
    int gph = t >> 1, k = t & 1;
    float cnt = (float)g_gcnt[gph];
    if (cnt < 1.f) cnt = 1.f;
    float s = 0.f;
    #pragma unroll
    for (int c = 0; c < C2; c++) s += g_gsum[gph * C2 + c] * Wc[c * NCLS + k];
    out[t] = s / cnt + bc[k];
}

// ---------------- launch ----------------
extern "C" void kernel_launch(void* const* d_in, const int* in_sizes, int n_in,
                              void* d_out, int out_size) {
    const float* x     = (const float*)d_in[0];
    const int*   ei    = (const int*)  d_in[1];   // [2, E] row-major
    const int*   batch = (const int*)  d_in[2];
    const float* W1    = (const float*)d_in[3];
    const float* atts1 = (const float*)d_in[4];
    const float* attd1 = (const float*)d_in[5];
    const float* b1    = (const float*)d_in[6];
    const float* W2    = (const float*)d_in[7];
    const float* atts2 = (const float*)d_in[8];
    const float* attd2 = (const float*)d_in[9];
    const float* b2    = (const float*)d_in[10];
    const float* Wc    = (const float*)d_in[11];
    const float* bc    = (const float*)d_in[12];
    float* out = (float*)d_out;

    int gemm_grid = (NN + MB - 1) / MB;   // 1563

    // order keeps gemm1 at the launch index ncu captures
    k_init   <<<(NN + 255) / 256, 256>>>();
    k_hist   <<<(EE / 4 + 255) / 256, 256>>>(ei + EE);
    k_prepW  <<<(3072 + 255) / 256, 256>>>(W1, W2);
    k_gemm1  <<<gemm_grid, 256>>>(x, atts1, attd1);
    k_scanA  <<<NCHUNK, 256>>>();
    k_scanB  <<<1, 512>>>(NCHUNK);
    k_scanC  <<<NCHUNK, 256>>>();
    k_scatter<<<(NETOT + 255) / 256, 256>>>(ei);

    k_agg1   <<<(NN * 32 + 255) / 256, 256>>>(b1);
    k_gemm2  <<<gemm_grid, 128>>>(atts2, attd2);
    k_agg2   <<<(NN * 32 + 255) / 256, 256>>>(b2);

    k_pool   <<<(NN + POOL_CHUNK - 1) / POOL_CHUNK, 64>>>(batch);
    k_final  <<<1, 128>>>(Wc, bc, out);
}

// round 6
// speedup vs baseline: 2.2522x; 1.0940x over previous
#include <cuda_runtime.h>
#include <cuda_fp16.h>
#include <math.h>
#include <stdint.h>

#define NN      100000
#define EE      1600000
#define NETOT   (EE + NN)           // edges + self loops
#define INC     128
#define C1      128                 // heads(4) * hid(32)
#define C2      64
#define HEADS   4
#define NGRAPH  64
#define NCLS    2
#define NCHUNK  ((NN + 255) / 256)  // 391
#define MB      64                  // gemm rows per block

// ---------------- scratch (static __device__, no allocations) ----------------
__device__ int    g_deg[NN];
__device__ int    g_rs[NN + 1];
__device__ int    g_cur[NN];
__device__ int    g_csr[NETOT];
__device__ int    g_csum[512];
__device__ __align__(16) __half g_h1h[NN * C1];
__device__ float  g_as1[NN * HEADS];
__device__ float  g_ad1[NN * HEADS];
__device__ __align__(16) __half g_x2h[NN * C1];
__device__ __align__(16) __half g_h2h[NN * C2];
__device__ float  g_as2[NN];
__device__ float  g_ad2[NN];
__device__ float  g_out2[NN * C2];
__device__ __align__(16) __half g_w1t[C1 * INC];   // W1^T fp16, ldsm-swizzled
__device__ __align__(16) __half g_w2t[C2 * C1];    // W2^T fp16, ldsm-swizzled

__device__ __forceinline__ float lrelu(float x) { return x > 0.f ? x : 0.2f * x; }
__device__ __forceinline__ float elu1(float x)  { return x > 0.f ? x : expm1f(x); }

__device__ __forceinline__ void ldsm4(uint32_t& r0, uint32_t& r1, uint32_t& r2, uint32_t& r3,
                                      uint32_t addr) {
    asm volatile("ldmatrix.sync.aligned.m8n8.x4.shared.b16 {%0,%1,%2,%3}, [%4];"
                 : "=r"(r0), "=r"(r1), "=r"(r2), "=r"(r3) : "r"(addr));
}
__device__ __forceinline__ void mma16816(float* c, const uint32_t* a, uint32_t b0, uint32_t b1) {
    asm volatile("mma.sync.aligned.m16n8k16.row.col.f32.f16.f16.f32 "
                 "{%0,%1,%2,%3},{%4,%5,%6,%7},{%8,%9},{%0,%1,%2,%3};"
                 : "+f"(c[0]), "+f"(c[1]), "+f"(c[2]), "+f"(c[3])
                 : "r"(a[0]), "r"(a[1]), "r"(a[2]), "r"(a[3]), "r"(b0), "r"(b1));
}

// ---------------- CSR build ----------------
__global__ void k_init() {
    int i = blockIdx.x * blockDim.x + threadIdx.x;
    if (i < NN) g_deg[i] = 1;                 // self loop pre-counted
}

__global__ void k_hist(const int* __restrict__ dst) {
    int e4 = blockIdx.x * blockDim.x + threadIdx.x;
    if (e4 * 4 + 3 < EE) {
        int4 d = *(const int4*)(dst + e4 * 4);
        atomicAdd(&g_deg[d.x], 1);
        atomicAdd(&g_deg[d.y], 1);
        atomicAdd(&g_deg[d.z], 1);
        atomicAdd(&g_deg[d.w], 1);
    } else {
        for (int e = e4 * 4; e < EE; e++) atomicAdd(&g_deg[dst[e]], 1);
    }
}

// one-time weight transpose + fp16 + ldsm swizzle bake
__global__ void k_prepW(const float* __restrict__ W1, const float* __restrict__ W2) {
    int idx = blockIdx.x * blockDim.x + threadIdx.x;
    if (idx < 128 * 16) {
        int n = idx >> 4, kc = idx & 15;
        int sc = kc ^ (n & 7);
        #pragma unroll
        for (int j = 0; j < 8; j++)
            g_w1t[n * 128 + (sc << 3) + j] = __float2half(W1[(kc * 8 + j) * C1 + n]);
    } else if (idx < 128 * 16 + 64 * 16) {
        int q = idx - 128 * 16;
        int n = q >> 4, kc = q & 15;
        int sc = kc ^ (n & 7);
        #pragma unroll
        for (int j = 0; j < 8; j++)
            g_w2t[n * 128 + (sc << 3) + j] = __float2half(W2[(kc * 8 + j) * C2 + n]);
    }
}

__global__ void k_scanA() {
    __shared__ int sh[256];
    int i = blockIdx.x * 256 + threadIdx.x;
    int v = (i < NN) ? g_deg[i] : 0;
    sh[threadIdx.x] = v;
    __syncthreads();
    #pragma unroll
    for (int off = 1; off < 256; off <<= 1) {
        int t = (threadIdx.x >= off) ? sh[threadIdx.x - off] : 0;
        __syncthreads();
        sh[threadIdx.x] += t;
        __syncthreads();
    }
    if (i < NN) g_rs[i] = sh[threadIdx.x] - v;     // chunk-local exclusive
    if (threadIdx.x == 255) g_csum[blockIdx.x] = sh[255];
}

__global__ void k_scanB(int nchunk) {
    __shared__ int sh[512];
    int t = threadIdx.x;
    int v = (t < nchunk) ? g_csum[t] : 0;
    sh[t] = v;
    __syncthreads();
    #pragma unroll
    for (int off = 1; off < 512; off <<= 1) {
        int tv = (t >= off) ? sh[t - off] : 0;
        __syncthreads();
        sh[t] += tv;
        __syncthreads();
    }
    if (t < nchunk) g_csum[t] = sh[t] - v;         // exclusive
}

__global__ void k_scanC() {
    int i = blockIdx.x * 256 + threadIdx.x;
    if (i < NN) {
        int r = g_rs[i] + g_csum[blockIdx.x];
        g_rs[i] = r;
        g_cur[i] = r;
    }
    if (i == 0) g_rs[NN] = NETOT;
}

__global__ void k_scatter(const int* __restrict__ ei) {
    int idx = blockIdx.x * blockDim.x + threadIdx.x;
    if (idx >= NETOT) return;
    int s, d;
    if (idx < EE) { s = ei[idx]; d = ei[EE + idx]; }
    else          { s = idx - EE; d = s; }
    int pos = atomicAdd(&g_cur[d], 1);
    g_csr[pos] = s;
}

// ---------------- GEMM1 (HMMA): h1 = x @ W1, fp16 out + attention scalars ----------------
// 256 threads = 8 warps, 64 rows/block. Warp grid 2(M) x 4(N); N-warp == head.
// Epilogue stages fragments in smem (XOR-swizzled, conflict-free) -> coalesced STG.128.
__global__ void __launch_bounds__(256) k_gemm1(
        const float* __restrict__ x,
        const float* __restrict__ att_s, const float* __restrict__ att_d) {
    __shared__ __align__(16) __half xs[MB * 128];     // 16KB; reused as stage buffer
    __shared__ __align__(16) __half ws[128 * 128];    // 32KB
    int tid = threadIdx.x;
    int row0 = blockIdx.x * MB;

    {
        const uint4* wsrc = (const uint4*)g_w1t;
        uint4* wdst = (uint4*)ws;
        #pragma unroll
        for (int i = 0; i < 8; i++) wdst[tid + 256 * i] = wsrc[tid + 256 * i];
    }
    #pragma unroll
    for (int i = 0; i < 4; i++) {
        int idx = tid + 256 * i;
        int m = idx >> 4, cc = idx & 15;
        int gm = row0 + m; if (gm > NN - 1) gm = NN - 1;
        const float4* xp = (const float4*)(x + gm * INC + cc * 8);
        float4 v0 = xp[0], v1 = xp[1];
        __half2 h0 = __floats2half2_rn(v0.x, v0.y);
        __half2 h1 = __floats2half2_rn(v0.z, v0.w);
        __half2 h2 = __floats2half2_rn(v1.x, v1.y);
        __half2 h3 = __floats2half2_rn(v1.z, v1.w);
        uint4 pk = make_uint4(*(unsigned*)&h0, *(unsigned*)&h1, *(unsigned*)&h2, *(unsigned*)&h3);
        int sc = cc ^ (m & 7);
        *(uint4*)(xs + m * 128 + sc * 8) = pk;
    }
    __syncthreads();

    int w = tid >> 5, lane = tid & 31;
    int mw = w >> 2, nw = w & 3;
    int i8 = lane >> 3, r8 = lane & 7;
    uint32_t xbase = (uint32_t)__cvta_generic_to_shared(xs);
    uint32_t wbase = (uint32_t)__cvta_generic_to_shared(ws);

    int rowA[2], rowB[2];
    #pragma unroll
    for (int mt = 0; mt < 2; mt++) rowA[mt] = mw * 32 + mt * 16 + (i8 & 1) * 8 + r8;
    #pragma unroll
    for (int p = 0; p < 2; p++)   rowB[p] = nw * 32 + p * 16 + (i8 >> 1) * 8 + r8;
    int kcA_off = (i8 >> 1);
    int kcB_off = (i8 & 1);

    float c[2][4][4];
    #pragma unroll
    for (int mt = 0; mt < 2; mt++)
        #pragma unroll
        for (int nt = 0; nt < 4; nt++)
            #pragma unroll
            for (int q = 0; q < 4; q++) c[mt][nt][q] = 0.f;

    #pragma unroll
    for (int kt = 0; kt < 8; kt++) {
        uint32_t A[2][4], B[2][4];
        #pragma unroll
        for (int mt = 0; mt < 2; mt++) {
            int kc = kt * 2 + kcA_off;
            uint32_t addr = xbase + rowA[mt] * 256 + (((kc ^ (rowA[mt] & 7))) << 4);
            ldsm4(A[mt][0], A[mt][1], A[mt][2], A[mt][3], addr);
        }
        #pragma unroll
        for (int p = 0; p < 2; p++) {
            int kc = kt * 2 + kcB_off;
            uint32_t addr = wbase + rowB[p] * 256 + (((kc ^ (rowB[p] & 7))) << 4);
            ldsm4(B[p][0], B[p][1], B[p][2], B[p][3], addr);
        }
        #pragma unroll
        for (int mt = 0; mt < 2; mt++) {
            mma16816(c[mt][0], A[mt], B[0][0], B[0][1]);
            mma16816(c[mt][1], A[mt], B[0][2], B[0][3]);
            mma16816(c[mt][2], A[mt], B[1][0], B[1][1]);
            mma16816(c[mt][3], A[mt], B[1][2], B[1][3]);
        }
    }
    __syncthreads();                                   // xs reads done; reuse as stage

    uint32_t* stg = (uint32_t*)xs;                     // 64 rows x 64 words
    int quad = lane & 3;
    #pragma unroll
    for (int mt = 0; mt < 2; mt++) {
        int rlo_l = mw * 32 + mt * 16 + (lane >> 2);
        int rhi_l = rlo_l + 8;
        int rlo = row0 + rlo_l, rhi = row0 + rhi_l;
        int sw = (rlo_l & 7) << 2;                     // same for rhi_l
        float slo = 0.f, shi = 0.f, dlo = 0.f, dhi = 0.f;
        #pragma unroll
        for (int nt = 0; nt < 4; nt++) {
            int cb = nw * 32 + nt * 8 + 2 * quad;
            float as0 = att_s[cb], as1 = att_s[cb + 1];
            float ad0 = att_d[cb], ad1 = att_d[cb + 1];
            float v0 = c[mt][nt][0], v1 = c[mt][nt][1];
            float v2 = c[mt][nt][2], v3 = c[mt][nt][3];
            slo += v0 * as0 + v1 * as1;  dlo += v0 * ad0 + v1 * ad1;
            shi += v2 * as0 + v3 * as1;  dhi += v2 * ad0 + v3 * ad1;
            int wcol = cb >> 1;                        // nw*16 + nt*4 + quad
            __half2 hlo = __floats2half2_rn(v0, v1);
            __half2 hhi = __floats2half2_rn(v2, v3);
            stg[rlo_l * 64 + (wcol ^ sw)] = *(uint32_t*)&hlo;
            stg[rhi_l * 64 + (wcol ^ sw)] = *(uint32_t*)&hhi;
        }
        #pragma unroll
        for (int o = 1; o <= 2; o <<= 1) {
            slo += __shfl_xor_sync(0xffffffffu, slo, o);
            shi += __shfl_xor_sync(0xffffffffu, shi, o);
            dlo += __shfl_xor_sync(0xffffffffu, dlo, o);
            dhi += __shfl_xor_sync(0xffffffffu, dhi, o);
        }
        if (quad == 0) {
            if (rlo < NN) { g_as1[rlo * 4 + nw] = slo; g_ad1[rlo * 4 + nw] = dlo; }
            if (rhi < NN) { g_as1[rhi * 4 + nw] = shi; g_ad1[rhi * 4 + nw] = dhi; }
        }
    }
    __syncthreads();
    #pragma unroll
    for (int i = 0; i < 4; i++) {
        int q = tid + 256 * i;                         // 1024 uint4
        int row = q >> 4, w4 = q & 15;
        int grow = row0 + row;
        uint4 v = *(uint4*)&stg[row * 64 + ((4 * w4) ^ ((row & 7) << 2))];
        if (grow < NN) *(uint4*)(g_h1h + grow * C1 + 8 * w4) = v;
    }
}

// ---------------- conv1 aggregation: one warp per dst node, single pass ----------------
__global__ void k_agg1(const float* __restrict__ b1) {
    int gw = (blockIdx.x * blockDim.x + threadIdx.x) >> 5;
    if (gw >= NN) return;
    int lane = threadIdx.x & 31;
    int beg = g_rs[gw], end = g_rs[gw + 1];
    int head = lane >> 3;                 // lane covers cols [4*lane, 4*lane+4)
    float adh = g_ad1[gw * 4 + head];

    float sum = 0.f;
    float4 acc = make_float4(0.f, 0.f, 0.f, 0.f);
    int j = beg;
    for (; j + 4 <= end; j += 4) {
        int s0 = g_csr[j],     s1 = g_csr[j + 1];
        int s2 = g_csr[j + 2], s3 = g_csr[j + 3];
        float a0 = g_as1[s0 * 4 + head];
        float a1 = g_as1[s1 * 4 + head];
        float a2 = g_as1[s2 * 4 + head];
        float a3 = g_as1[s3 * 4 + head];
        uint2 u0 = *(const uint2*)(g_h1h + s0 * C1 + lane * 4);
        uint2 u1 = *(const uint2*)(g_h1h + s1 * C1 + lane * 4);
        uint2 u2 = *(const uint2*)(g_h1h + s2 * C1 + lane * 4);
        uint2 u3 = *(const uint2*)(g_h1h + s3 * C1 + lane * 4);
        float e0 = __expf(lrelu(a0 + adh));
        float e1 = __expf(lrelu(a1 + adh));
        float e2 = __expf(lrelu(a2 + adh));
        float e3 = __expf(lrelu(a3 + adh));
        sum += (e0 + e1) + (e2 + e3);
        float2 f0a = __half22float2(*(__half2*)&u0.x), f0b = __half22float2(*(__half2*)&u0.y);
        float2 f1a = __half22float2(*(__half2*)&u1.x), f1b = __half22float2(*(__half2*)&u1.y);
        float2 f2a = __half22float2(*(__half2*)&u2.x), f2b = __half22float2(*(__half2*)&u2.y);
        float2 f3a = __half22float2(*(__half2*)&u3.x), f3b = __half22float2(*(__half2*)&u3.y);
        acc.x += e0 * f0a.x + e1 * f1a.x + e2 * f2a.x + e3 * f3a.x;
        acc.y += e0 * f0a.y + e1 * f1a.y + e2 * f2a.y + e3 * f3a.y;
        acc.z += e0 * f0b.x + e1 * f1b.x + e2 * f2b.x + e3 * f3b.x;
        acc.w += e0 * f0b.y + e1 * f1b.y + e2 * f2b.y + e3 * f3b.y;
    }
    for (; j < end; j++) {
        int s = g_csr[j];
        float e = __expf(lrelu(g_as1[s * 4 + head] + adh));
        sum += e;
        uint2 u = *(const uint2*)(g_h1h + s * C1 + lane * 4);
        float2 fa = __half22float2(*(__half2*)&u.x);
        float2 fb = __half22float2(*(__half2*)&u.y);
        acc.x += e * fa.x; acc.y += e * fa.y;
        acc.z += e * fb.x; acc.w += e * fb.y;
    }
    float inv = 1.0f / (sum + 1e-16f);
    float4 bv = *(const float4*)(b1 + lane * 4);
    __half2 p0 = __floats2half2_rn(elu1(acc.x * inv + bv.x), elu1(acc.y * inv + bv.y));
    __half2 p1 = __floats2half2_rn(elu1(acc.z * inv + bv.z), elu1(acc.w * inv + bv.w));
    *(uint2*)(g_x2h + gw * C1 + lane * 4) = make_uint2(*(unsigned*)&p0, *(unsigned*)&p1);
}

// ---------------- GEMM2 (HMMA): h2 = x2 @ W2, fp16 out + attention scalars ----------------
// 128 threads = 4 warps, 64 rows/block. Warp grid 2(M) x 2(N).
__global__ void __launch_bounds__(128) k_gemm2(
        const float* __restrict__ att_s, const float* __restrict__ att_d) {
    __shared__ __align__(16) __half xs[MB * 128];    // 16KB; reused as stage
    __shared__ __align__(16) __half ws[C2 * 128];    // 16KB
    __shared__ float s_part[2][MB], d_part[2][MB];
    int tid = threadIdx.x;
    int row0 = blockIdx.x * MB;

    {
        const uint4* wsrc = (const uint4*)g_w2t;
        uint4* wdst = (uint4*)ws;
        #pragma unroll
        for (int i = 0; i < 8; i++) wdst[tid + 128 * i] = wsrc[tid + 128 * i];
    }
    #pragma unroll
    for (int i = 0; i < 8; i++) {
        int idx = tid + 128 * i;
        int m = idx >> 4, cc = idx & 15;
        int gm = row0 + m; if (gm > NN - 1) gm = NN - 1;
        uint4 pk = *(const uint4*)(g_x2h + gm * C1 + cc * 8);
        int sc = cc ^ (m & 7);
        *(uint4*)(xs + m * 128 + sc * 8) = pk;
    }
    __syncthreads();

    int w = tid >> 5, lane = tid & 31;
    int mw = w >> 1, nw = w & 1;
    int i8 = lane >> 3, r8 = lane & 7;
    uint32_t xbase = (uint32_t)__cvta_generic_to_shared(xs);
    uint32_t wbase = (uint32_t)__cvta_generic_to_shared(ws);

    int rowA[2], rowB[2];
    #pragma unroll
    for (int mt = 0; mt < 2; mt++) rowA[mt] = mw * 32 + mt * 16 + (i8 & 1) * 8 + r8;
    #pragma unroll
    for (int p = 0; p < 2; p++)   rowB[p] = nw * 32 + p * 16 + (i8 >> 1) * 8 + r8;
    int kcA_off = (i8 >> 1), kcB_off = (i8 & 1);

    float c[2][4][4];
    #pragma unroll
    for (int mt = 0; mt < 2; mt++)
        #pragma unroll
        for (int nt = 0; nt < 4; nt++)
            #pragma unroll
            for (int q = 0; q < 4; q++) c[mt][nt][q] = 0.f;

    #pragma unroll
    for (int kt = 0; kt < 8; kt++) {
        uint32_t A[2][4], B[2][4];
        #pragma unroll
        for (int mt = 0; mt < 2; mt++) {
            int kc = kt * 2 + kcA_off;
            uint32_t addr = xbase + rowA[mt] * 256 + (((kc ^ (rowA[mt] & 7))) << 4);
            ldsm4(A[mt][0], A[mt][1], A[mt][2], A[mt][3], addr);
        }
        #pragma unroll
        for (int p = 0; p < 2; p++) {
            int kc = kt * 2 + kcB_off;
            uint32_t addr = wbase + rowB[p] * 256 + (((kc ^ (rowB[p] & 7))) << 4);
            ldsm4(B[p][0], B[p][1], B[p][2], B[p][3], addr);
        }
        #pragma unroll
        for (int mt = 0; mt < 2; mt++) {
            mma16816(c[mt][0], A[mt], B[0][0], B[0][1]);
            mma16816(c[mt][1], A[mt], B[0][2], B[0][3]);
            mma16816(c[mt][2], A[mt], B[1][0], B[1][1]);
            mma16816(c[mt][3], A[mt], B[1][2], B[1][3]);
        }
    }
    __syncthreads();                                   // xs reads done; reuse as stage

    uint32_t* stg = (uint32_t*)xs;                     // 64 rows x 32 words
    int quad = lane & 3;
    #pragma unroll
    for (int mt = 0; mt < 2; mt++) {
        int rlo_l = mw * 32 + mt * 16 + (lane >> 2);
        int rhi_l = rlo_l + 8;
        int sw = (rlo_l & 7) << 2;
        float slo = 0.f, shi = 0.f, dlo = 0.f, dhi = 0.f;
        #pragma unroll
        for (int nt = 0; nt < 4; nt++) {
            int cb = nw * 32 + nt * 8 + 2 * quad;
            float as0 = att_s[cb], as1 = att_s[cb + 1];
            float ad0 = att_d[cb], ad1 = att_d[cb + 1];
            float v0 = c[mt][nt][0], v1 = c[mt][nt][1];
            float v2 = c[mt][nt][2], v3 = c[mt][nt][3];
            slo += v0 * as0 + v1 * as1;  dlo += v0 * ad0 + v1 * ad1;
            shi += v2 * as0 + v3 * as1;  dhi += v2 * ad0 + v3 * ad1;
            int wcol = cb >> 1;                        // 0..31
            __half2 hlo = __floats2half2_rn(v0, v1);
            __half2 hhi = __floats2half2_rn(v2, v3);
            stg[rlo_l * 32 + (wcol ^ sw)] = *(uint32_t*)&hlo;
            stg[rhi_l * 32 + (wcol ^ sw)] = *(uint32_t*)&hhi;
        }
        #pragma unroll
        for (int o = 1; o <= 2; o <<= 1) {
            slo += __shfl_xor_sync(0xffffffffu, slo, o);
            shi += __shfl_xor_sync(0xffffffffu, shi, o);
            dlo += __shfl_xor_sync(0xffffffffu, dlo, o);
            dhi += __shfl_xor_sync(0xffffffffu, dhi, o);
        }
        if (quad == 0) {
            s_part[nw][rlo_l] = slo;  d_part[nw][rlo_l] = dlo;
            s_part[nw][rhi_l] = shi;  d_part[nw][rhi_l] = dhi;
        }
    }
    __syncthreads();
    #pragma unroll
    for (int i = 0; i < 4; i++) {
        int q = tid + 128 * i;                         // 512 uint4
        int row = q >> 3, w4 = q & 7;
        int grow = row0 + row;
        uint4 v = *(uint4*)&stg[row * 32 + ((4 * w4) ^ ((row & 7) << 2))];
        if (grow < NN) *(uint4*)(g_h2h + grow * C2 + 8 * w4) = v;
    }
    if (tid < MB) {
        int row = row0 + tid;
        if (row < NN) {
            g_as2[row] = s_part[0][tid] + s_part[1][tid];
            g_ad2[row] = d_part[0][tid] + d_part[1][tid];
        }
    }
}

// ---------------- conv2 aggregation: one warp per node, single pass ----------------
__global__ void k_agg2(const float* __restrict__ b2) {
    int gw = (blockIdx.x * blockDim.x + threadIdx.x) >> 5;
    if (gw >= NN) return;
    int lane = threadIdx.x & 31;
    int beg = g_rs[gw], end = g_rs[gw + 1];
    float ad = g_ad2[gw];

    float sum = 0.f;
    float2 acc = make_float2(0.f, 0.f);
    int j = beg;
    for (; j + 4 <= end; j += 4) {
        int s0 = g_csr[j],     s1 = g_csr[j + 1];
        int s2 = g_csr[j + 2], s3 = g_csr[j + 3];
        float a0 = g_as2[s0], a1 = g_as2[s1];
        float a2 = g_as2[s2], a3 = g_as2[s3];
        __half2 u0 = *(const __half2*)(g_h2h + s0 * C2 + lane * 2);
        __half2 u1 = *(const __half2*)(g_h2h + s1 * C2 + lane * 2);
        __half2 u2 = *(const __half2*)(g_h2h + s2 * C2 + lane * 2);
        __half2 u3 = *(const __half2*)(g_h2h + s3 * C2 + lane * 2);
        float e0 = __expf(lrelu(a0 + ad));
        float e1 = __expf(lrelu(a1 + ad));
        float e2 = __expf(lrelu(a2 + ad));
        float e3 = __expf(lrelu(a3 + ad));
        sum += (e0 + e1) + (e2 + e3);
        float2 f0 = __half22float2(u0), f1 = __half22float2(u1);
        float2 f2 = __half22float2(u2), f3 = __half22float2(u3);
        acc.x += e0 * f0.x + e1 * f1.x + e2 * f2.x + e3 * f3.x;
        acc.y += e0 * f0.y + e1 * f1.y + e2 * f2.y + e3 * f3.y;
    }
    for (; j < end; j++) {
        int s = g_csr[j];
        float e = __expf(lrelu(g_as2[s] + ad));
        sum += e;
        float2 f = __half22float2(*(const __half2*)(g_h2h + s * C2 + lane * 2));
        acc.x += e * f.x; acc.y += e * f.y;
    }
    float inv = 1.0f / (sum + 1e-16f);
    float2 bv = *(const float2*)(b2 + lane * 2);
    float2 o;
    o.x = elu1(acc.x * inv + bv.x);
    o.y = elu1(acc.y * inv + bv.y);
    *(float2*)(g_out2 + gw * C2 + lane * 2) = o;
}

// ---------------- fused global mean pool + classifier (1 block per graph) ----------------
__global__ void __launch_bounds__(256) k_poolfinal(
        const int* __restrict__ batch, const float* __restrict__ Wc,
        const float* __restrict__ bc, float* __restrict__ out) {
    __shared__ int sb[2];
    __shared__ float red[4][C2];
    __shared__ float pooled[C2];
    int g = blockIdx.x, tid = threadIdx.x;
    if (tid < 2) {
        int target = g + tid;
        int lo = 0, hi = NN;
        while (lo < hi) { int mid = (lo + hi) >> 1; if (batch[mid] < target) lo = mid + 1; else hi = mid; }
        sb[tid] = lo;
    }
    __syncthreads();
    int lo = sb[0], hi = sb[1];
    int ch = tid & 63, grp = tid >> 6;
    float a0 = 0.f, a1 = 0.f;
    int n = lo + grp;
    for (; n + 4 < hi; n += 8) {
        a0 += g_out2[n * C2 + ch];
        a1 += g_out2[(n + 4) * C2 + ch];
    }
    if (n < hi) a0 += g_out2[n * C2 + ch];
    red[grp][ch] = a0 + a1;
    __syncthreads();
    if (tid < C2) {
        float cnt = (float)(hi - lo); if (cnt < 1.f) cnt = 1.f;
        pooled[tid] = (red[0][tid] + red[1][tid] + red[2][tid] + red[3][tid]) / cnt;
    }
    __syncthreads();
    if (tid < NCLS) {
        float s = 0.f;
        #pragma unroll
        for (int c2 = 0; c2 < C2; c2++) s += pooled[c2] * Wc[c2 * NCLS + tid];
        out[g * NCLS + tid] = s + bc[tid];
    }
}

// ---------------- launch ----------------
extern "C" void kernel_launch(void* const* d_in, const int* in_sizes, int n_in,
                              void* d_out, int out_size) {
    const float* x     = (const float*)d_in[0];
    const int*   ei    = (const int*)  d_in[1];   // [2, E] row-major
    const int*   batch = (const int*)  d_in[2];
    const float* W1    = (const float*)d_in[3];
    const float* atts1 = (const float*)d_in[4];
    const float* attd1 = (const float*)d_in[5];
    const float* b1    = (const float*)d_in[6];
    const float* W2    = (const float*)d_in[7];
    const float* atts2 = (const float*)d_in[8];
    const float* attd2 = (const float*)d_in[9];
    const float* b2    = (const float*)d_in[10];
    const float* Wc    = (const float*)d_in[11];
    const float* bc    = (const float*)d_in[12];
    float* out = (float*)d_out;

    int gemm_grid = (NN + MB - 1) / MB;   // 1563

    // order keeps gemm1 at the launch index ncu captures (4th)
    k_init     <<<(NN + 255) / 256, 256>>>();
    k_hist     <<<(EE / 4 + 255) / 256, 256>>>(ei + EE);
    k_prepW    <<<(3072 + 255) / 256, 256>>>(W1, W2);
    k_gemm1    <<<gemm_grid, 256>>>(x, atts1, attd1);
    k_scanA    <<<NCHUNK, 256>>>();
    k_scanB    <<<1, 512>>>(NCHUNK);
    k_scanC    <<<NCHUNK, 256>>>();
    k_scatter  <<<(NETOT + 255) / 256, 256>>>(ei);

    k_agg1     <<<(NN * 32 + 255) / 256, 256>>>(b1);
    k_gemm2    <<<gemm_grid, 128>>>(atts2, attd2);
    k_agg2     <<<(NN * 32 + 255) / 256, 256>>>(b2);

    k_poolfinal<<<NGRAPH, 256>>>(batch, Wc, bc, out);
}

// round 8
// speedup vs baseline: 2.2570x; 1.0021x over previous
#include <cuda_runtime.h>
#include <cuda_fp16.h>
#include <math.h>
#include <stdint.h>

#define NN      100000
#define EE      1600000
#define NETOT   (EE + NN)           // edges + self loops
#define INC     128
#define C1      128                 // heads(4) * hid(32)
#define C2      64
#define HEADS   4
#define NGRAPH  64
#define NCLS    2
#define NCHUNK  ((NN + 255) / 256)  // 391
#define MB      64                  // gemm rows per block

// ---------------- scratch (static __device__, no allocations) ----------------
__device__ int    g_deg[NN];        // zero at entry (BSS-zero; re-zeroed by scanC each call)
__device__ int    g_rs[NN + 1];
__device__ int    g_cur[NN];
__device__ int    g_csr[NETOT];
__device__ int    g_csum[512];
__device__ __align__(16) __half g_h1h[NN * C1];
__device__ float  g_as1[NN * HEADS];
__device__ float  g_ad1[NN * HEADS];
__device__ __align__(16) __half g_x2h[NN * C1];
__device__ __align__(16) __half g_h2h[NN * C2];
__device__ float  g_as2[NN];
__device__ float  g_ad2[NN];
__device__ __align__(16) __half g_out2h[NN * C2];
__device__ __align__(16) __half g_w1t[C1 * INC];   // W1^T fp16, ldsm-swizzled
__device__ __align__(16) __half g_w2t[C2 * C1];    // W2^T fp16, ldsm-swizzled

__device__ __forceinline__ float lrelu(float x) { return x > 0.f ? x : 0.2f * x; }
__device__ __forceinline__ float elu1(float x)  { return x > 0.f ? x : expm1f(x); }

__device__ __forceinline__ void ldsm4(uint32_t& r0, uint32_t& r1, uint32_t& r2, uint32_t& r3,
                                      uint32_t addr) {
    asm volatile("ldmatrix.sync.aligned.m8n8.x4.shared.b16 {%0,%1,%2,%3}, [%4];"
                 : "=r"(r0), "=r"(r1), "=r"(r2), "=r"(r3) : "r"(addr));
}
__device__ __forceinline__ void mma16816(float* c, const uint32_t* a, uint32_t b0, uint32_t b1) {
    asm volatile("mma.sync.aligned.m16n8k16.row.col.f32.f16.f16.f32 "
                 "{%0,%1,%2,%3},{%4,%5,%6,%7},{%8,%9},{%0,%1,%2,%3};"
                 : "+f"(c[0]), "+f"(c[1]), "+f"(c[2]), "+f"(c[3])
                 : "r"(a[0]), "r"(a[1]), "r"(a[2]), "r"(a[3]), "r"(b0), "r"(b1));
}

// ---------------- CSR build ----------------
__global__ void k_hist(const int* __restrict__ dst) {
    int e4 = blockIdx.x * blockDim.x + threadIdx.x;
    if (e4 * 4 + 3 < EE) {
        int4 d = *(const int4*)(dst + e4 * 4);
        atomicAdd(&g_deg[d.x], 1);
        atomicAdd(&g_deg[d.y], 1);
        atomicAdd(&g_deg[d.z], 1);
        atomicAdd(&g_deg[d.w], 1);
    } else {
        for (int e = e4 * 4; e < EE; e++) atomicAdd(&g_deg[dst[e]], 1);
    }
}

__global__ void k_scanA() {
    __shared__ int sh[256];
    int i = blockIdx.x * 256 + threadIdx.x;
    int v = (i < NN) ? (g_deg[i] + 1) : 0;    // +1 = self loop
    sh[threadIdx.x] = v;
    __syncthreads();
    #pragma unroll
    for (int off = 1; off < 256; off <<= 1) {
        int t = (threadIdx.x >= off) ? sh[threadIdx.x - off] : 0;
        __syncthreads();
        sh[threadIdx.x] += t;
        __syncthreads();
    }
    if (i < NN) g_rs[i] = sh[threadIdx.x] - v;     // chunk-local exclusive
    if (threadIdx.x == 255) g_csum[blockIdx.x] = sh[255];
}

// merged scanB+scanC: every block redundantly scans the 391 chunk sums
// in shared, then applies offsets to its 512 rows (2 chunks per block).
__global__ void __launch_bounds__(512) k_scanC() {
    __shared__ int sh[512];
    int t = threadIdx.x;
    int v = (t < NCHUNK) ? g_csum[t] : 0;
    sh[t] = v;
    __syncthreads();
    #pragma unroll
    for (int off = 1; off < 512; off <<= 1) {
        int tv = (t >= off) ? sh[t - off] : 0;
        __syncthreads();
        sh[t] += tv;
        __syncthreads();
    }
    sh[t] -= v;                                    // exclusive
    __syncthreads();
    int i = blockIdx.x * 512 + t;
    if (i < NN) {
        int r = g_rs[i] + sh[i >> 8];
        g_rs[i] = r;
        g_cur[i] = r;
        g_deg[i] = 0;                              // reset for next invocation
    }
    if (i == 0) g_rs[NN] = NETOT;
}

__global__ void k_scatter(const int* __restrict__ ei) {
    int idx = blockIdx.x * blockDim.x + threadIdx.x;
    if (idx >= NETOT) return;
    int s, d;
    if (idx < EE) { s = ei[idx]; d = ei[EE + idx]; }
    else          { s = idx - EE; d = s; }
    int pos = atomicAdd(&g_cur[d], 1);
    g_csr[pos] = s;
}

// one-time weight transpose + fp16 + ldsm swizzle bake
__global__ void k_prepW(const float* __restrict__ W1, const float* __restrict__ W2) {
    int idx = blockIdx.x * blockDim.x + threadIdx.x;
    if (idx < 128 * 16) {
        int n = idx >> 4, kc = idx & 15;
        int sc = kc ^ (n & 7);
        #pragma unroll
        for (int j = 0; j < 8; j++)
            g_w1t[n * 128 + (sc << 3) + j] = __float2half(W1[(kc * 8 + j) * C1 + n]);
    } else if (idx < 128 * 16 + 64 * 16) {
        int q = idx - 128 * 16;
        int n = q >> 4, kc = q & 15;
        int sc = kc ^ (n & 7);
        #pragma unroll
        for (int j = 0; j < 8; j++)
            g_w2t[n * 128 + (sc << 3) + j] = __float2half(W2[(kc * 8 + j) * C2 + n]);
    }
}

// ---------------- GEMM1 (HMMA): h1 = x @ W1, fp16 out + attention scalars ----------------
// 256 threads = 8 warps, 64 rows/block. Warp grid 2(M) x 4(N); N-warp == head.
__global__ void __launch_bounds__(256) k_gemm1(
        const float* __restrict__ x,
        const float* __restrict__ att_s, const float* __restrict__ att_d) {
    __shared__ __align__(16) __half xs[MB * 128];     // 16KB; reused as stage buffer
    __shared__ __align__(16) __half ws[128 * 128];    // 32KB
    int tid = threadIdx.x;
    int row0 = blockIdx.x * MB;

    {
        const uint4* wsrc = (const uint4*)g_w1t;
        uint4* wdst = (uint4*)ws;
        #pragma unroll
        for (int i = 0; i < 8; i++) wdst[tid + 256 * i] = wsrc[tid + 256 * i];
    }
    #pragma unroll
    for (int i = 0; i < 4; i++) {
        int idx = tid + 256 * i;
        int m = idx >> 4, cc = idx & 15;
        int gm = row0 + m; if (gm > NN - 1) gm = NN - 1;
        const float4* xp = (const float4*)(x + gm * INC + cc * 8);
        float4 v0 = xp[0], v1 = xp[1];
        __half2 h0 = __floats2half2_rn(v0.x, v0.y);
        __half2 h1 = __floats2half2_rn(v0.z, v0.w);
        __half2 h2 = __floats2half2_rn(v1.x, v1.y);
        __half2 h3 = __floats2half2_rn(v1.z, v1.w);
        uint4 pk = make_uint4(*(unsigned*)&h0, *(unsigned*)&h1, *(unsigned*)&h2, *(unsigned*)&h3);
        int sc = cc ^ (m & 7);
        *(uint4*)(xs + m * 128 + sc * 8) = pk;
    }
    __syncthreads();

    int w = tid >> 5, lane = tid & 31;
    int mw = w >> 2, nw = w & 3;
    int i8 = lane >> 3, r8 = lane & 7;
    uint32_t xbase = (uint32_t)__cvta_generic_to_shared(xs);
    uint32_t wbase = (uint32_t)__cvta_generic_to_shared(ws);

    int rowA[2], rowB[2];
    #pragma unroll
    for (int mt = 0; mt < 2; mt++) rowA[mt] = mw * 32 + mt * 16 + (i8 & 1) * 8 + r8;
    #pragma unroll
    for (int p = 0; p < 2; p++)   rowB[p] = nw * 32 + p * 16 + (i8 >> 1) * 8 + r8;
    int kcA_off = (i8 >> 1);
    int kcB_off = (i8 & 1);

    float c[2][4][4];
    #pragma unroll
    for (int mt = 0; mt < 2; mt++)
        #pragma unroll
        for (int nt = 0; nt < 4; nt++)
            #pragma unroll
            for (int q = 0; q < 4; q++) c[mt][nt][q] = 0.f;

    #pragma unroll
    for (int kt = 0; kt < 8; kt++) {
        uint32_t A[2][4], B[2][4];
        #pragma unroll
        for (int mt = 0; mt < 2; mt++) {
            int kc = kt * 2 + kcA_off;
            uint32_t addr = xbase + rowA[mt] * 256 + (((kc ^ (rowA[mt] & 7))) << 4);
            ldsm4(A[mt][0], A[mt][1], A[mt][2], A[mt][3], addr);
        }
        #pragma unroll
        for (int p = 0; p < 2; p++) {
            int kc = kt * 2 + kcB_off;
            uint32_t addr = wbase + rowB[p] * 256 + (((kc ^ (rowB[p] & 7))) << 4);
            ldsm4(B[p][0], B[p][1], B[p][2], B[p][3], addr);
        }
        #pragma unroll
        for (int mt = 0; mt < 2; mt++) {
            mma16816(c[mt][0], A[mt], B[0][0], B[0][1]);
            mma16816(c[mt][1], A[mt], B[0][2], B[0][3]);
            mma16816(c[mt][2], A[mt], B[1][0], B[1][1]);
            mma16816(c[mt][3], A[mt], B[1][2], B[1][3]);
        }
    }
    __syncthreads();                                   // xs reads done; reuse as stage

    uint32_t* stg = (uint32_t*)xs;                     // 64 rows x 64 words
    int quad = lane & 3;
    #pragma unroll
    for (int mt = 0; mt < 2; mt++) {
        int rlo_l = mw * 32 + mt * 16 + (lane >> 2);
        int rhi_l = rlo_l + 8;
        int rlo = row0 + rlo_l, rhi = row0 + rhi_l;
        int sw = (rlo_l & 7) << 2;                     // same for rhi_l
        float slo = 0.f, shi = 0.f, dlo = 0.f, dhi = 0.f;
        #pragma unroll
        for (int nt = 0; nt < 4; nt++) {
            int cb = nw * 32 + nt * 8 + 2 * quad;
            float as0 = att_s[cb], as1 = att_s[cb + 1];
            float ad0 = att_d[cb], ad1 = att_d[cb + 1];
            float v0 = c[mt][nt][0], v1 = c[mt][nt][1];
            float v2 = c[mt][nt][2], v3 = c[mt][nt][3];
            slo += v0 * as0 + v1 * as1;  dlo += v0 * ad0 + v1 * ad1;
            shi += v2 * as0 + v3 * as1;  dhi += v2 * ad0 + v3 * ad1;
            int wcol = cb >> 1;
            __half2 hlo = __floats2half2_rn(v0, v1);
            __half2 hhi = __floats2half2_rn(v2, v3);
            stg[rlo_l * 64 + (wcol ^ sw)] = *(uint32_t*)&hlo;
            stg[rhi_l * 64 + (wcol ^ sw)] = *(uint32_t*)&hhi;
        }
        #pragma unroll
        for (int o = 1; o <= 2; o <<= 1) {
            slo += __shfl_xor_sync(0xffffffffu, slo, o);
            shi += __shfl_xor_sync(0xffffffffu, shi, o);
            dlo += __shfl_xor_sync(0xffffffffu, dlo, o);
            dhi += __shfl_xor_sync(0xffffffffu, dhi, o);
        }
        if (quad == 0) {
            if (rlo < NN) { g_as1[rlo * 4 + nw] = slo; g_ad1[rlo * 4 + nw] = dlo; }
            if (rhi < NN) { g_as1[rhi * 4 + nw] = shi; g_ad1[rhi * 4 + nw] = dhi; }
        }
    }
    __syncthreads();
    #pragma unroll
    for (int i = 0; i < 4; i++) {
        int q = tid + 256 * i;                         // 1024 uint4
        int row = q >> 4, w4 = q & 15;
        int grow = row0 + row;
        uint4 v = *(uint4*)&stg[row * 64 + ((4 * w4) ^ ((row & 7) << 2))];
        if (grow < NN) *(uint4*)(g_h1h + grow * C1 + 8 * w4) = v;
    }
}

// ---------------- conv1 aggregation: one warp per dst node, single pass ----------------
__global__ void k_agg1(const float* __restrict__ b1) {
    int gw = (blockIdx.x * blockDim.x + threadIdx.x) >> 5;
    if (gw >= NN) return;
    int lane = threadIdx.x & 31;
    int beg = g_rs[gw], end = g_rs[gw + 1];
    int head = lane >> 3;                 // lane covers cols [4*lane, 4*lane+4)
    float adh = g_ad1[gw * 4 + head];

    float sum = 0.f;
    float4 acc = make_float4(0.f, 0.f, 0.f, 0.f);
    int j = beg;
    for (; j + 4 <= end; j += 4) {
        int s0 = g_csr[j],     s1 = g_csr[j + 1];
        int s2 = g_csr[j + 2], s3 = g_csr[j + 3];
        float a0 = g_as1[s0 * 4 + head];
        float a1 = g_as1[s1 * 4 + head];
        float a2 = g_as1[s2 * 4 + head];
        float a3 = g_as1[s3 * 4 + head];
        uint2 u0 = *(const uint2*)(g_h1h + s0 * C1 + lane * 4);
        uint2 u1 = *(const uint2*)(g_h1h + s1 * C1 + lane * 4);
        uint2 u2 = *(const uint2*)(g_h1h + s2 * C1 + lane * 4);
        uint2 u3 = *(const uint2*)(g_h1h + s3 * C1 + lane * 4);
        float e0 = __expf(lrelu(a0 + adh));
        float e1 = __expf(lrelu(a1 + adh));
        float e2 = __expf(lrelu(a2 + adh));
        float e3 = __expf(lrelu(a3 + adh));
        sum += (e0 + e1) + (e2 + e3);
        float2 f0a = __half22float2(*(__half2*)&u0.x), f0b = __half22float2(*(__half2*)&u0.y);
        float2 f1a = __half22float2(*(__half2*)&u1.x), f1b = __half22float2(*(__half2*)&u1.y);
        float2 f2a = __half22float2(*(__half2*)&u2.x), f2b = __half22float2(*(__half2*)&u2.y);
        float2 f3a = __half22float2(*(__half2*)&u3.x), f3b = __half22float2(*(__half2*)&u3.y);
        acc.x += e0 * f0a.x + e1 * f1a.x + e2 * f2a.x + e3 * f3a.x;
        acc.y += e0 * f0a.y + e1 * f1a.y + e2 * f2a.y + e3 * f3a.y;
        acc.z += e0 * f0b.x + e1 * f1b.x + e2 * f2b.x + e3 * f3b.x;
        acc.w += e0 * f0b.y + e1 * f1b.y + e2 * f2b.y + e3 * f3b.y;
    }
    for (; j < end; j++) {
        int s = g_csr[j];
        float e = __expf(lrelu(g_as1[s * 4 + head] + adh));
        sum += e;
        uint2 u = *(const uint2*)(g_h1h + s * C1 + lane * 4);
        float2 fa = __half22float2(*(__half2*)&u.x);
        float2 fb = __half22float2(*(__half2*)&u.y);
        acc.x += e * fa.x; acc.y += e * fa.y;
        acc.z += e * fb.x; acc.w += e * fb.y;
    }
    float inv = 1.0f / (sum + 1e-16f);
    float4 bv = *(const float4*)(b1 + lane * 4);
    __half2 p0 = __floats2half2_rn(elu1(acc.x * inv + bv.x), elu1(acc.y * inv + bv.y));
    __half2 p1 = __floats2half2_rn(elu1(acc.z * inv + bv.z), elu1(acc.w * inv + bv.w));
    *(uint2*)(g_x2h + gw * C1 + lane * 4) = make_uint2(*(unsigned*)&p0, *(unsigned*)&p1);
}

// ---------------- GEMM2 (HMMA): h2 = x2 @ W2, fp16 out + attention scalars ----------------
// 128 threads = 4 warps, 64 rows/block. Warp grid 2(M) x 2(N).
__global__ void __launch_bounds__(128) k_gemm2(
        const float* __restrict__ att_s, const float* __restrict__ att_d) {
    __shared__ __align__(16) __half xs[MB * 128];    // 16KB; reused as stage
    __shared__ __align__(16) __half ws[C2 * 128];    // 16KB
    __shared__ float s_part[2][MB], d_part[2][MB];
    int tid = threadIdx.x;
    int row0 = blockIdx.x * MB;

    {
        const uint4* wsrc = (const uint4*)g_w2t;
        uint4* wdst = (uint4*)ws;
        #pragma unroll
        for (int i = 0; i < 8; i++) wdst[tid + 128 * i] = wsrc[tid + 128 * i];
    }
    #pragma unroll
    for (int i = 0; i < 8; i++) {
        int idx = tid + 128 * i;
        int m = idx >> 4, cc = idx & 15;
        int gm = row0 + m; if (gm > NN - 1) gm = NN - 1;
        uint4 pk = *(const uint4*)(g_x2h + gm * C1 + cc * 8);
        int sc = cc ^ (m & 7);
        *(uint4*)(xs + m * 128 + sc * 8) = pk;
    }
    __syncthreads();

    int w = tid >> 5, lane = tid & 31;
    int mw = w >> 1, nw = w & 1;
    int i8 = lane >> 3, r8 = lane & 7;
    uint32_t xbase = (uint32_t)__cvta_generic_to_shared(xs);
    uint32_t wbase = (uint32_t)__cvta_generic_to_shared(ws);

    int rowA[2], rowB[2];
    #pragma unroll
    for (int mt = 0; mt < 2; mt++) rowA[mt] = mw * 32 + mt * 16 + (i8 & 1) * 8 + r8;
    #pragma unroll
    for (int p = 0; p < 2; p++)   rowB[p] = nw * 32 + p * 16 + (i8 >> 1) * 8 + r8;
    int kcA_off = (i8 >> 1), kcB_off = (i8 & 1);

    float c[2][4][4];
    #pragma unroll
    for (int mt = 0; mt < 2; mt++)
        #pragma unroll
        for (int nt = 0; nt < 4; nt++)
            #pragma unroll
            for (int q = 0; q < 4; q++) c[mt][nt][q] = 0.f;

    #pragma unroll
    for (int kt = 0; kt < 8; kt++) {
        uint32_t A[2][4], B[2][4];
        #pragma unroll
        for (int mt = 0; mt < 2; mt++) {
            int kc = kt * 2 + kcA_off;
            uint32_t addr = xbase + rowA[mt] * 256 + (((kc ^ (rowA[mt] & 7))) << 4);
            ldsm4(A[mt][0], A[mt][1], A[mt][2], A[mt][3], addr);
        }
        #pragma unroll
        for (int p = 0; p < 2; p++) {
            int kc = kt * 2 + kcB_off;
            uint32_t addr = wbase + rowB[p] * 256 + (((kc ^ (rowB[p] & 7))) << 4);
            ldsm4(B[p][0], B[p][1], B[p][2], B[p][3], addr);
        }
        #pragma unroll
        for (int mt = 0; mt < 2; mt++) {
            mma16816(c[mt][0], A[mt], B[0][0], B[0][1]);
            mma16816(c[mt][1], A[mt], B[0][2], B[0][3]);
            mma16816(c[mt][2], A[mt], B[1][0], B[1][1]);
            mma16816(c[mt][3], A[mt], B[1][2], B[1][3]);
        }
    }
    __syncthreads();                                   // xs reads done; reuse as stage

    uint32_t* stg = (uint32_t*)xs;                     // 64 rows x 32 words
    int quad = lane & 3;
    #pragma unroll
    for (int mt = 0; mt < 2; mt++) {
        int rlo_l = mw * 32 + mt * 16 + (lane >> 2);
        int rhi_l = rlo_l + 8;
        int sw = (rlo_l & 7) << 2;
        float slo = 0.f, shi = 0.f, dlo = 0.f, dhi = 0.f;
        #pragma unroll
        for (int nt = 0; nt < 4; nt++) {
            int cb = nw * 32 + nt * 8 + 2 * quad;
            float as0 = att_s[cb], as1 = att_s[cb + 1];
            float ad0 = att_d[cb], ad1 = att_d[cb + 1];
            float v0 = c[mt][nt][0], v1 = c[mt][nt][1];
            float v2 = c[mt][nt][2], v3 = c[mt][nt][3];
            slo += v0 * as0 + v1 * as1;  dlo += v0 * ad0 + v1 * ad1;
            shi += v2 * as0 + v3 * as1;  dhi += v2 * ad0 + v3 * ad1;
            int wcol = cb >> 1;                        // 0..31
            __half2 hlo = __floats2half2_rn(v0, v1);
            __half2 hhi = __floats2half2_rn(v2, v3);
            stg[rlo_l * 32 + (wcol ^ sw)] = *(uint32_t*)&hlo;
            stg[rhi_l * 32 + (wcol ^ sw)] = *(uint32_t*)&hhi;
        }
        #pragma unroll
        for (int o = 1; o <= 2; o <<= 1) {
            slo += __shfl_xor_sync(0xffffffffu, slo, o);
            shi += __shfl_xor_sync(0xffffffffu, shi, o);
            dlo += __shfl_xor_sync(0xffffffffu, dlo, o);
            dhi += __shfl_xor_sync(0xffffffffu, dhi, o);
        }
        if (quad == 0) {
            s_part[nw][rlo_l] = slo;  d_part[nw][rlo_l] = dlo;
            s_part[nw][rhi_l] = shi;  d_part[nw][rhi_l] = dhi;
        }
    }
    __syncthreads();
    #pragma unroll
    for (int i = 0; i < 4; i++) {
        int q = tid + 128 * i;                         // 512 uint4
        int row = q >> 3, w4 = q & 7;
        int grow = row0 + row;
        uint4 v = *(uint4*)&stg[row * 32 + ((4 * w4) ^ ((row & 7) << 2))];
        if (grow < NN) *(uint4*)(g_h2h + grow * C2 + 8 * w4) = v;
    }
    if (tid < MB) {
        int row = row0 + tid;
        if (row < NN) {
            g_as2[row] = s_part[0][tid] + s_part[1][tid];
            g_ad2[row] = d_part[0][tid] + d_part[1][tid];
        }
    }
}

// ---------------- conv2 aggregation: one warp per node, single pass ----------------
__global__ void k_agg2(const float* __restrict__ b2) {
    int gw = (blockIdx.x * blockDim.x + threadIdx.x) >> 5;
    if (gw >= NN) return;
    int lane = threadIdx.x & 31;
    int beg = g_rs[gw], end = g_rs[gw + 1];
    float ad = g_ad2[gw];

    float sum = 0.f;
    float2 acc = make_float2(0.f, 0.f);
    int j = beg;
    for (; j + 4 <= end; j += 4) {
        int s0 = g_csr[j],     s1 = g_csr[j + 1];
        int s2 = g_csr[j + 2], s3 = g_csr[j + 3];
        float a0 = g_as2[s0], a1 = g_as2[s1];
        float a2 = g_as2[s2], a3 = g_as2[s3];
        __half2 u0 = *(const __half2*)(g_h2h + s0 * C2 + lane * 2);
        __half2 u1 = *(const __half2*)(g_h2h + s1 * C2 + lane * 2);
        __half2 u2 = *(const __half2*)(g_h2h + s2 * C2 + lane * 2);
        __half2 u3 = *(const __half2*)(g_h2h + s3 * C2 + lane * 2);
        float e0 = __expf(lrelu(a0 + ad));
        float e1 = __expf(lrelu(a1 + ad));
        float e2 = __expf(lrelu(a2 + ad));
        float e3 = __expf(lrelu(a3 + ad));
        sum += (e0 + e1) + (e2 + e3);
        float2 f0 = __half22float2(u0), f1 = __half22float2(u1);
        float2 f2 = __half22float2(u2), f3 = __half22float2(u3);
        acc.x += e0 * f0.x + e1 * f1.x + e2 * f2.x + e3 * f3.x;
        acc.y += e0 * f0.y + e1 * f1.y + e2 * f2.y + e3 * f3.y;
    }
    for (; j < end; j++) {
        int s = g_csr[j];
        float e = __expf(lrelu(g_as2[s] + ad));
        sum += e;
        float2 f = __half22float2(*(const __half2*)(g_h2h + s * C2 + lane * 2));
        acc.x += e * f.x; acc.y += e * f.y;
    }
    float inv = 1.0f / (sum + 1e-16f);
    float2 bv = *(const float2*)(b2 + lane * 2);
    __half2 o = __floats2half2_rn(elu1(acc.x * inv + bv.x), elu1(acc.y * inv + bv.y));
    *(__half2*)(g_out2h + gw * C2 + lane * 2) = o;
}

// ---------------- fused global mean pool + classifier (1 block per graph) ----------------
__global__ void __launch_bounds__(256) k_poolfinal(
        const int* __restrict__ batch, const float* __restrict__ Wc,
        const float* __restrict__ bc, float* __restrict__ out) {
    __shared__ int sb[2];
    __shared__ float red[4][C2];
    __shared__ float pooled[C2];
    int g = blockIdx.x, tid = threadIdx.x;
    if (tid < 2) {
        int target = g + tid;
        int lo = 0, hi = NN;
        while (lo < hi) { int mid = (lo + hi) >> 1; if (batch[mid] < target) lo = mid + 1; else hi = mid; }
        sb[tid] = lo;
    }
    __syncthreads();
    int lo = sb[0], hi = sb[1];
    int ch = tid & 63, grp = tid >> 6;
    float a0 = 0.f, a1 = 0.f;
    int n = lo + grp;
    for (; n + 4 < hi; n += 8) {
        a0 += __half2float(g_out2h[n * C2 + ch]);
        a1 += __half2float(g_out2h[(n + 4) * C2 + ch]);
    }
    if (n < hi) a0 += __half2float(g_out2h[n * C2 + ch]);
    red[grp][ch] = a0 + a1;
    __syncthreads();
    if (tid < C2) {
        float cnt = (float)(hi - lo); if (cnt < 1.f) cnt = 1.f;
        pooled[tid] = (red[0][tid] + red[1][tid] + red[2][tid] + red[3][tid]) / cnt;
    }
    __syncthreads();
    if (tid < NCLS) {
        float s = 0.f;
        #pragma unroll
        for (int c2 = 0; c2 < C2; c2++) s += pooled[c2] * Wc[c2 * NCLS + tid];
        out[g * NCLS + tid] = s + bc[tid];
    }
}

// ---------------- launch ----------------
extern "C" void kernel_launch(void* const* d_in, const int* in_sizes, int n_in,
                              void* d_out, int out_size) {
    const float* x     = (const float*)d_in[0];
    const int*   ei    = (const int*)  d_in[1];   // [2, E] row-major
    const int*   batch = (const int*)  d_in[2];
    const float* W1    = (const float*)d_in[3];
    const float* atts1 = (const float*)d_in[4];
    const float* attd1 = (const float*)d_in[5];
    const float* b1    = (const float*)d_in[6];
    const float* W2    = (const float*)d_in[7];
    const float* atts2 = (const float*)d_in[8];
    const float* attd2 = (const float*)d_in[9];
    const float* b2    = (const float*)d_in[10];
    const float* Wc    = (const float*)d_in[11];
    const float* bc    = (const float*)d_in[12];
    float* out = (float*)d_out;

    int gemm_grid = (NN + MB - 1) / MB;   // 1563

    // launch order puts k_scatter at idx 3 (the slot ncu captures)
    k_hist     <<<(EE / 4 + 255) / 256, 256>>>(ei + EE);
    k_scanA    <<<NCHUNK, 256>>>();
    k_scanC    <<<(NN + 511) / 512, 512>>>();
    k_scatter  <<<(NETOT + 255) / 256, 256>>>(ei);
    k_prepW    <<<(3072 + 255) / 256, 256>>>(W1, W2);
    k_gemm1    <<<gemm_grid, 256>>>(x, atts1, attd1);

    k_agg1     <<<(NN * 32 + 255) / 256, 256>>>(b1);
    k_gemm2    <<<gemm_grid, 128>>>(atts2, attd2);
    k_agg2     <<<(NN * 32 + 255) / 256, 256>>>(b2);

    k_poolfinal<<<NGRAPH, 256>>>(batch, Wc, bc, out);
}

// round 9
// speedup vs baseline: 2.2712x; 1.0063x over previous
#include <cuda_runtime.h>
#include <cuda_fp16.h>
#include <math.h>
#include <stdint.h>

#define NN      100000
#define EE      1600000
#define NETOT   (EE + NN)           // edges + self loops
#define INC     128
#define C1      128                 // heads(4) * hid(32)
#define C2      64
#define HEADS   4
#define NGRAPH  64
#define NCLS    2
#define NCHUNK  ((NN + 255) / 256)  // 391
#define MB      64                  // gemm rows per block

// ---------------- scratch (static __device__, no allocations) ----------------
__device__ int    g_deg[NN];        // zero at entry (BSS-zero; re-zeroed by scanC each call)
__device__ int    g_rs[NN + 1];
__device__ int    g_epos[EE];       // per-edge slot within its dst segment
__device__ int    g_csr[NETOT];
__device__ int    g_csum[512];
__device__ __align__(16) __half g_h1h[NN * C1];
__device__ float  g_as1[NN * HEADS];
__device__ float  g_ad1[NN * HEADS];
__device__ __align__(16) __half g_x2h[NN * C1];
__device__ __align__(16) __half g_h2h[NN * C2];
__device__ float  g_as2[NN];
__device__ float  g_ad2[NN];
__device__ __align__(16) __half g_out2h[NN * C2];
__device__ __align__(16) __half g_w1t[C1 * INC];   // W1^T fp16, ldsm-swizzled
__device__ __align__(16) __half g_w2t[C2 * C1];    // W2^T fp16, ldsm-swizzled

__device__ __forceinline__ float lrelu(float x) { return x > 0.f ? x : 0.2f * x; }
__device__ __forceinline__ float elu1(float x)  { return x > 0.f ? x : expm1f(x); }

__device__ __forceinline__ void ldsm4(uint32_t& r0, uint32_t& r1, uint32_t& r2, uint32_t& r3,
                                      uint32_t addr) {
    asm volatile("ldmatrix.sync.aligned.m8n8.x4.shared.b16 {%0,%1,%2,%3}, [%4];"
                 : "=r"(r0), "=r"(r1), "=r"(r2), "=r"(r3) : "r"(addr));
}
__device__ __forceinline__ void mma16816(float* c, const uint32_t* a, uint32_t b0, uint32_t b1) {
    asm volatile("mma.sync.aligned.m16n8k16.row.col.f32.f16.f16.f32 "
                 "{%0,%1,%2,%3},{%4,%5,%6,%7},{%8,%9},{%0,%1,%2,%3};"
                 : "+f"(c[0]), "+f"(c[1]), "+f"(c[2]), "+f"(c[3])
                 : "r"(a[0]), "r"(a[1]), "r"(a[2]), "r"(a[3]), "r"(b0), "r"(b1));
}

// ---------------- CSR build ----------------
// hist: count degrees AND record each edge's slot within its destination segment
__global__ void k_hist(const int* __restrict__ dst) {
    int e4 = blockIdx.x * blockDim.x + threadIdx.x;
    int e = e4 * 4;
    if (e + 3 < EE) {
        int4 d = *(const int4*)(dst + e);
        int4 p;
        p.x = atomicAdd(&g_deg[d.x], 1);
        p.y = atomicAdd(&g_deg[d.y], 1);
        p.z = atomicAdd(&g_deg[d.z], 1);
        p.w = atomicAdd(&g_deg[d.w], 1);
        *(int4*)(g_epos + e) = p;
    } else {
        for (; e < EE; e++) g_epos[e] = atomicAdd(&g_deg[dst[e]], 1);
    }
}

__global__ void k_scanA() {
    __shared__ int sh[256];
    int i = blockIdx.x * 256 + threadIdx.x;
    int v = (i < NN) ? (g_deg[i] + 1) : 0;    // +1 = self loop
    sh[threadIdx.x] = v;
    __syncthreads();
    #pragma unroll
    for (int off = 1; off < 256; off <<= 1) {
        int t = (threadIdx.x >= off) ? sh[threadIdx.x - off] : 0;
        __syncthreads();
        sh[threadIdx.x] += t;
        __syncthreads();
    }
    if (i < NN) g_rs[i] = sh[threadIdx.x] - v;     // chunk-local exclusive
    if (threadIdx.x == 255) g_csum[blockIdx.x] = sh[255];
}

// merged scanB+scanC: every block redundantly scans the 391 chunk sums.
__global__ void __launch_bounds__(512) k_scanC() {
    __shared__ int sh[512];
    int t = threadIdx.x;
    int v = (t < NCHUNK) ? g_csum[t] : 0;
    sh[t] = v;
    __syncthreads();
    #pragma unroll
    for (int off = 1; off < 512; off <<= 1) {
        int tv = (t >= off) ? sh[t - off] : 0;
        __syncthreads();
        sh[t] += tv;
        __syncthreads();
    }
    sh[t] -= v;                                    // exclusive
    __syncthreads();
    int i = blockIdx.x * 512 + t;
    if (i < NN) {
        g_rs[i] += sh[i >> 8];
        g_deg[i] = 0;                              // reset for next invocation
    }
    if (i == 0) g_rs[NN] = NETOT;
}

// scatter: NO atomics — position = rs[dst] + epos[e]; self loop at rs[d+1]-1
#define SCAT_E4 (EE / 4)                           // 400000 (exact)
__global__ void k_scatter(const int* __restrict__ ei) {
    int idx = blockIdx.x * blockDim.x + threadIdx.x;
    if (idx < SCAT_E4) {
        int e = idx * 4;
        int4 s = *(const int4*)(ei + e);
        int4 d = *(const int4*)(ei + EE + e);
        int4 p = *(const int4*)(g_epos + e);
        g_csr[g_rs[d.x] + p.x] = s.x;
        g_csr[g_rs[d.y] + p.y] = s.y;
        g_csr[g_rs[d.z] + p.z] = s.z;
        g_csr[g_rs[d.w] + p.w] = s.w;
    } else {
        int n = idx - SCAT_E4;
        if (n < NN) g_csr[g_rs[n + 1] - 1] = n;    // self loop
    }
}

// one-time weight transpose + fp16 + ldsm swizzle bake
__global__ void k_prepW(const float* __restrict__ W1, const float* __restrict__ W2) {
    int idx = blockIdx.x * blockDim.x + threadIdx.x;
    if (idx < 128 * 16) {
        int n = idx >> 4, kc = idx & 15;
        int sc = kc ^ (n & 7);
        #pragma unroll
        for (int j = 0; j < 8; j++)
            g_w1t[n * 128 + (sc << 3) + j] = __float2half(W1[(kc * 8 + j) * C1 + n]);
    } else if (idx < 128 * 16 + 64 * 16) {
        int q = idx - 128 * 16;
        int n = q >> 4, kc = q & 15;
        int sc = kc ^ (n & 7);
        #pragma unroll
        for (int j = 0; j < 8; j++)
            g_w2t[n * 128 + (sc << 3) + j] = __float2half(W2[(kc * 8 + j) * C2 + n]);
    }
}

// ---------------- GEMM1 (HMMA): h1 = x @ W1, fp16 out + attention scalars ----------------
__global__ void __launch_bounds__(256) k_gemm1(
        const float* __restrict__ x,
        const float* __restrict__ att_s, const float* __restrict__ att_d) {
    __shared__ __align__(16) __half xs[MB * 128];     // 16KB; reused as stage buffer
    __shared__ __align__(16) __half ws[128 * 128];    // 32KB
    int tid = threadIdx.x;
    int row0 = blockIdx.x * MB;

    {
        const uint4* wsrc = (const uint4*)g_w1t;
        uint4* wdst = (uint4*)ws;
        #pragma unroll
        for (int i = 0; i < 8; i++) wdst[tid + 256 * i] = wsrc[tid + 256 * i];
    }
    #pragma unroll
    for (int i = 0; i < 4; i++) {
        int idx = tid + 256 * i;
        int m = idx >> 4, cc = idx & 15;
        int gm = row0 + m; if (gm > NN - 1) gm = NN - 1;
        const float4* xp = (const float4*)(x + gm * INC + cc * 8);
        float4 v0 = xp[0], v1 = xp[1];
        __half2 h0 = __floats2half2_rn(v0.x, v0.y);
        __half2 h1 = __floats2half2_rn(v0.z, v0.w);
        __half2 h2 = __floats2half2_rn(v1.x, v1.y);
        __half2 h3 = __floats2half2_rn(v1.z, v1.w);
        uint4 pk = make_uint4(*(unsigned*)&h0, *(unsigned*)&h1, *(unsigned*)&h2, *(unsigned*)&h3);
        int sc = cc ^ (m & 7);
        *(uint4*)(xs + m * 128 + sc * 8) = pk;
    }
    __syncthreads();

    int w = tid >> 5, lane = tid & 31;
    int mw = w >> 2, nw = w & 3;
    int i8 = lane >> 3, r8 = lane & 7;
    uint32_t xbase = (uint32_t)__cvta_generic_to_shared(xs);
    uint32_t wbase = (uint32_t)__cvta_generic_to_shared(ws);

    int rowA[2], rowB[2];
    #pragma unroll
    for (int mt = 0; mt < 2; mt++) rowA[mt] = mw * 32 + mt * 16 + (i8 & 1) * 8 + r8;
    #pragma unroll
    for (int p = 0; p < 2; p++)   rowB[p] = nw * 32 + p * 16 + (i8 >> 1) * 8 + r8;
    int kcA_off = (i8 >> 1);
    int kcB_off = (i8 & 1);

    float c[2][4][4];
    #pragma unroll
    for (int mt = 0; mt < 2; mt++)
        #pragma unroll
        for (int nt = 0; nt < 4; nt++)
            #pragma unroll
            for (int q = 0; q < 4; q++) c[mt][nt][q] = 0.f;

    #pragma unroll
    for (int kt = 0; kt < 8; kt++) {
        uint32_t A[2][4], B[2][4];
        #pragma unroll
        for (int mt = 0; mt < 2; mt++) {
            int kc = kt * 2 + kcA_off;
            uint32_t addr = xbase + rowA[mt] * 256 + (((kc ^ (rowA[mt] & 7))) << 4);
            ldsm4(A[mt][0], A[mt][1], A[mt][2], A[mt][3], addr);
        }
        #pragma unroll
        for (int p = 0; p < 2; p++) {
            int kc = kt * 2 + kcB_off;
            uint32_t addr = wbase + rowB[p] * 256 + (((kc ^ (rowB[p] & 7))) << 4);
            ldsm4(B[p][0], B[p][1], B[p][2], B[p][3], addr);
        }
        #pragma unroll
        for (int mt = 0; mt < 2; mt++) {
            mma16816(c[mt][0], A[mt], B[0][0], B[0][1]);
            mma16816(c[mt][1], A[mt], B[0][2], B[0][3]);
            mma16816(c[mt][2], A[mt], B[1][0], B[1][1]);
            mma16816(c[mt][3], A[mt], B[1][2], B[1][3]);
        }
    }
    __syncthreads();                                   // xs reads done; reuse as stage

    uint32_t* stg = (uint32_t*)xs;                     // 64 rows x 64 words
    int quad = lane & 3;
    #pragma unroll
    for (int mt = 0; mt < 2; mt++) {
        int rlo_l = mw * 32 + mt * 16 + (lane >> 2);
        int rhi_l = rlo_l + 8;
        int rlo = row0 + rlo_l, rhi = row0 + rhi_l;
        int sw = (rlo_l & 7) << 2;                     // same for rhi_l
        float slo = 0.f, shi = 0.f, dlo = 0.f, dhi = 0.f;
        #pragma unroll
        for (int nt = 0; nt < 4; nt++) {
            int cb = nw * 32 + nt * 8 + 2 * quad;
            float as0 = att_s[cb], as1 = att_s[cb + 1];
            float ad0 = att_d[cb], ad1 = att_d[cb + 1];
            float v0 = c[mt][nt][0], v1 = c[mt][nt][1];
            float v2 = c[mt][nt][2], v3 = c[mt][nt][3];
            slo += v0 * as0 + v1 * as1;  dlo += v0 * ad0 + v1 * ad1;
            shi += v2 * as0 + v3 * as1;  dhi += v2 * ad0 + v3 * ad1;
            int wcol = cb >> 1;
            __half2 hlo = __floats2half2_rn(v0, v1);
            __half2 hhi = __floats2half2_rn(v2, v3);
            stg[rlo_l * 64 + (wcol ^ sw)] = *(uint32_t*)&hlo;
            stg[rhi_l * 64 + (wcol ^ sw)] = *(uint32_t*)&hhi;
        }
        #pragma unroll
        for (int o = 1; o <= 2; o <<= 1) {
            slo += __shfl_xor_sync(0xffffffffu, slo, o);
            shi += __shfl_xor_sync(0xffffffffu, shi, o);
            dlo += __shfl_xor_sync(0xffffffffu, dlo, o);
            dhi += __shfl_xor_sync(0xffffffffu, dhi, o);
        }
        if (quad == 0) {
            if (rlo < NN) { g_as1[rlo * 4 + nw] = slo; g_ad1[rlo * 4 + nw] = dlo; }
            if (rhi < NN) { g_as1[rhi * 4 + nw] = shi; g_ad1[rhi * 4 + nw] = dhi; }
        }
    }
    __syncthreads();
    #pragma unroll
    for (int i = 0; i < 4; i++) {
        int q = tid + 256 * i;                         // 1024 uint4
        int row = q >> 4, w4 = q & 15;
        int grow = row0 + row;
        uint4 v = *(uint4*)&stg[row * 64 + ((4 * w4) ^ ((row & 7) << 2))];
        if (grow < NN) *(uint4*)(g_h1h + grow * C1 + 8 * w4) = v;
    }
}

// ---------------- conv1 aggregation: one warp per dst node, pipelined gathers ----------------
__global__ void k_agg1(const float* __restrict__ b1) {
    int gw = (blockIdx.x * blockDim.x + threadIdx.x) >> 5;
    if (gw >= NN) return;
    int lane = threadIdx.x & 31;
    int beg = g_rs[gw], end = g_rs[gw + 1];
    int head = lane >> 3;                 // lane covers cols [4*lane, 4*lane+4)
    float adh = g_ad1[gw * 4 + head];

    float sum = 0.f;
    float4 acc = make_float4(0.f, 0.f, 0.f, 0.f);
    int j = beg;
    int jend4 = beg + ((end - beg) & ~3);

    if (j < jend4) {
        // prologue: load group 0
        int s0 = g_csr[j], s1 = g_csr[j+1], s2 = g_csr[j+2], s3 = g_csr[j+3];
        float a0 = g_as1[s0*4+head], a1 = g_as1[s1*4+head];
        float a2 = g_as1[s2*4+head], a3 = g_as1[s3*4+head];
        uint2 u0 = *(const uint2*)(g_h1h + s0*C1 + lane*4);
        uint2 u1 = *(const uint2*)(g_h1h + s1*C1 + lane*4);
        uint2 u2 = *(const uint2*)(g_h1h + s2*C1 + lane*4);
        uint2 u3 = *(const uint2*)(g_h1h + s3*C1 + lane*4);
        for (j += 4; j < jend4; j += 4) {
            // issue next group's loads first (independent of current math)
            int t0 = g_csr[j], t1 = g_csr[j+1], t2 = g_csr[j+2], t3 = g_csr[j+3];
            float b0n = g_as1[t0*4+head], b1n = g_as1[t1*4+head];
            float b2n = g_as1[t2*4+head], b3n = g_as1[t3*4+head];
            uint2 v0 = *(const uint2*)(g_h1h + t0*C1 + lane*4);
            uint2 v1 = *(const uint2*)(g_h1h + t1*C1 + lane*4);
            uint2 v2 = *(const uint2*)(g_h1h + t2*C1 + lane*4);
            uint2 v3 = *(const uint2*)(g_h1h + t3*C1 + lane*4);
            // consume current group
            float e0 = __expf(lrelu(a0 + adh));
            float e1 = __expf(lrelu(a1 + adh));
            float e2 = __expf(lrelu(a2 + adh));
            float e3 = __expf(lrelu(a3 + adh));
            sum += (e0 + e1) + (e2 + e3);
            float2 f0a = __half22float2(*(__half2*)&u0.x), f0b = __half22float2(*(__half2*)&u0.y);
            float2 f1a = __half22float2(*(__half2*)&u1.x), f1b = __half22float2(*(__half2*)&u1.y);
            float2 f2a = __half22float2(*(__half2*)&u2.x), f2b = __half22float2(*(__half2*)&u2.y);
            float2 f3a = __half22float2(*(__half2*)&u3.x), f3b = __half22float2(*(__half2*)&u3.y);
            acc.x += e0 * f0a.x + e1 * f1a.x + e2 * f2a.x + e3 * f3a.x;
            acc.y += e0 * f0a.y + e1 * f1a.y + e2 * f2a.y + e3 * f3a.y;
            acc.z += e0 * f0b.x + e1 * f1b.x + e2 * f2b.x + e3 * f3b.x;
            acc.w += e0 * f0b.y + e1 * f1b.y + e2 * f2b.y + e3 * f3b.y;
            // rotate
            a0 = b0n; a1 = b1n; a2 = b2n; a3 = b3n;
            u0 = v0; u1 = v1; u2 = v2; u3 = v3;
        }
        // epilogue: consume last group
        float e0 = __expf(lrelu(a0 + adh));
        float e1 = __expf(lrelu(a1 + adh));
        float e2 = __expf(lrelu(a2 + adh));
        float e3 = __expf(lrelu(a3 + adh));
        sum += (e0 + e1) + (e2 + e3);
        float2 f0a = __half22float2(*(__half2*)&u0.x), f0b = __half22float2(*(__half2*)&u0.y);
        float2 f1a = __half22float2(*(__half2*)&u1.x), f1b = __half22float2(*(__half2*)&u1.y);
        float2 f2a = __half22float2(*(__half2*)&u2.x), f2b = __half22float2(*(__half2*)&u2.y);
        float2 f3a = __half22float2(*(__half2*)&u3.x), f3b = __half22float2(*(__half2*)&u3.y);
        acc.x += e0 * f0a.x + e1 * f1a.x + e2 * f2a.x + e3 * f3a.x;
        acc.y += e0 * f0a.y + e1 * f1a.y + e2 * f2a.y + e3 * f3a.y;
        acc.z += e0 * f0b.x + e1 * f1b.x + e2 * f2b.x + e3 * f3b.x;
        acc.w += e0 * f0b.y + e1 * f1b.y + e2 * f2b.y + e3 * f3b.y;
    }
    for (; j < end; j++) {
        int s = g_csr[j];
        float e = __expf(lrelu(g_as1[s * 4 + head] + adh));
        sum += e;
        uint2 u = *(const uint2*)(g_h1h + s * C1 + lane * 4);
        float2 fa = __half22float2(*(__half2*)&u.x);
        float2 fb = __half22float2(*(__half2*)&u.y);
        acc.x += e * fa.x; acc.y += e * fa.y;
        acc.z += e * fb.x; acc.w += e * fb.y;
    }
    float inv = 1.0f / (sum + 1e-16f);
    float4 bv = *(const float4*)(b1 + lane * 4);
    __half2 p0 = __floats2half2_rn(elu1(acc.x * inv + bv.x), elu1(acc.y * inv + bv.y));
    __half2 p1 = __floats2half2_rn(elu1(acc.z * inv + bv.z), elu1(acc.w * inv + bv.w));
    *(uint2*)(g_x2h + gw * C1 + lane * 4) = make_uint2(*(unsigned*)&p0, *(unsigned*)&p1);
}

// ---------------- GEMM2 (HMMA): h2 = x2 @ W2, fp16 out + attention scalars ----------------
__global__ void __launch_bounds__(128) k_gemm2(
        const float* __restrict__ att_s, const float* __restrict__ att_d) {
    __shared__ __align__(16) __half xs[MB * 128];    // 16KB; reused as stage
    __shared__ __align__(16) __half ws[C2 * 128];    // 16KB
    __shared__ float s_part[2][MB], d_part[2][MB];
    int tid = threadIdx.x;
    int row0 = blockIdx.x * MB;

    {
        const uint4* wsrc = (const uint4*)g_w2t;
        uint4* wdst = (uint4*)ws;
        #pragma unroll
        for (int i = 0; i < 8; i++) wdst[tid + 128 * i] = wsrc[tid + 128 * i];
    }
    #pragma unroll
    for (int i = 0; i < 8; i++) {
        int idx = tid + 128 * i;
        int m = idx >> 4, cc = idx & 15;
        int gm = row0 + m; if (gm > NN - 1) gm = NN - 1;
        uint4 pk = *(const uint4*)(g_x2h + gm * C1 + cc * 8);
        int sc = cc ^ (m & 7);
        *(uint4*)(xs + m * 128 + sc * 8) = pk;
    }
    __syncthreads();

    int w = tid >> 5, lane = tid & 31;
    int mw = w >> 1, nw = w & 1;
    int i8 = lane >> 3, r8 = lane & 7;
    uint32_t xbase = (uint32_t)__cvta_generic_to_shared(xs);
    uint32_t wbase = (uint32_t)__cvta_generic_to_shared(ws);

    int rowA[2], rowB[2];
    #pragma unroll
    for (int mt = 0; mt < 2; mt++) rowA[mt] = mw * 32 + mt * 16 + (i8 & 1) * 8 + r8;
    #pragma unroll
    for (int p = 0; p < 2; p++)   rowB[p] = nw * 32 + p * 16 + (i8 >> 1) * 8 + r8;
    int kcA_off = (i8 >> 1), kcB_off = (i8 & 1);

    float c[2][4][4];
    #pragma unroll
    for (int mt = 0; mt < 2; mt++)
        #pragma unroll
        for (int nt = 0; nt < 4; nt++)
            #pragma unroll
            for (int q = 0; q < 4; q++) c[mt][nt][q] = 0.f;

    #pragma unroll
    for (int kt = 0; kt < 8; kt++) {
        uint32_t A[2][4], B[2][4];
        #pragma unroll
        for (int mt = 0; mt < 2; mt++) {
            int kc = kt * 2 + kcA_off;
            uint32_t addr = xbase + rowA[mt] * 256 + (((kc ^ (rowA[mt] & 7))) << 4);
            ldsm4(A[mt][0], A[mt][1], A[mt][2], A[mt][3], addr);
        }
        #pragma unroll
        for (int p = 0; p < 2; p++) {
            int kc = kt * 2 + kcB_off;
            uint32_t addr = wbase + rowB[p] * 256 + (((kc ^ (rowB[p] & 7))) << 4);
            ldsm4(B[p][0], B[p][1], B[p][2], B[p][3], addr);
        }
        #pragma unroll
        for (int mt = 0; mt < 2; mt++) {
            mma16816(c[mt][0], A[mt], B[0][0], B[0][1]);
            mma16816(c[mt][1], A[mt], B[0][2], B[0][3]);
            mma16816(c[mt][2], A[mt], B[1][0], B[1][1]);
            mma16816(c[mt][3], A[mt], B[1][2], B[1][3]);
        }
    }
    __syncthreads();                                   // xs reads done; reuse as stage

    uint32_t* stg = (uint32_t*)xs;                     // 64 rows x 32 words
    int quad = lane & 3;
    #pragma unroll
    for (int mt = 0; mt < 2; mt++) {
        int rlo_l = mw * 32 + mt * 16 + (lane >> 2);
        int rhi_l = rlo_l + 8;
        int sw = (rlo_l & 7) << 2;
        float slo = 0.f, shi = 0.f, dlo = 0.f, dhi = 0.f;
        #pragma unroll
        for (int nt = 0; nt < 4; nt++) {
            int cb = nw * 32 + nt * 8 + 2 * quad;
            float as0 = att_s[cb], as1 = att_s[cb + 1];
            float ad0 = att_d[cb], ad1 = att_d[cb + 1];
            float v0 = c[mt][nt][0], v1 = c[mt][nt][1];
            float v2 = c[mt][nt][2], v3 = c[mt][nt][3];
            slo += v0 * as0 + v1 * as1;  dlo += v0 * ad0 + v1 * ad1;
            shi += v2 * as0 + v3 * as1;  dhi += v2 * ad0 + v3 * ad1;
            int wcol = cb >> 1;                        // 0..31
            __half2 hlo = __floats2half2_rn(v0, v1);
            __half2 hhi = __floats2half2_rn(v2, v3);
            stg[rlo_l * 32 + (wcol ^ sw)] = *(uint32_t*)&hlo;
            stg[rhi_l * 32 + (wcol ^ sw)] = *(uint32_t*)&hhi;
        }
        #pragma unroll
        for (int o = 1; o <= 2; o <<= 1) {
            slo += __shfl_xor_sync(0xffffffffu, slo, o);
            shi += __shfl_xor_sync(0xffffffffu, shi, o);
            dlo += __shfl_xor_sync(0xffffffffu, dlo, o);
            dhi += __shfl_xor_sync(0xffffffffu, dhi, o);
        }
        if (quad == 0) {
            s_part[nw][rlo_l] = slo;  d_part[nw][rlo_l] = dlo;
            s_part[nw][rhi_l] = shi;  d_part[nw][rhi_l] = dhi;
        }
    }
    __syncthreads();
    #pragma unroll
    for (int i = 0; i < 4; i++) {
        int q = tid + 128 * i;                         // 512 uint4
        int row = q >> 3, w4 = q & 7;
        int grow = row0 + row;
        uint4 v = *(uint4*)&stg[row * 32 + ((4 * w4) ^ ((row & 7) << 2))];
        if (grow < NN) *(uint4*)(g_h2h + grow * C2 + 8 * w4) = v;
    }
    if (tid < MB) {
        int row = row0 + tid;
        if (row < NN) {
            g_as2[row] = s_part[0][tid] + s_part[1][tid];
            g_ad2[row] = d_part[0][tid] + d_part[1][tid];
        }
    }
}

// ---------------- conv2 aggregation: one warp per node, pipelined gathers ----------------
__global__ void k_agg2(const float* __restrict__ b2) {
    int gw = (blockIdx.x * blockDim.x + threadIdx.x) >> 5;
    if (gw >= NN) return;
    int lane = threadIdx.x & 31;
    int beg = g_rs[gw], end = g_rs[gw + 1];
    float ad = g_ad2[gw];

    float sum = 0.f;
    float2 acc = make_float2(0.f, 0.f);
    int j = beg;
    int jend4 = beg + ((end - beg) & ~3);

    if (j < jend4) {
        int s0 = g_csr[j], s1 = g_csr[j+1], s2 = g_csr[j+2], s3 = g_csr[j+3];
        float a0 = g_as2[s0], a1 = g_as2[s1], a2 = g_as2[s2], a3 = g_as2[s3];
        __half2 u0 = *(const __half2*)(g_h2h + s0*C2 + lane*2);
        __half2 u1 = *(const __half2*)(g_h2h + s1*C2 + lane*2);
        __half2 u2 = *(const __half2*)(g_h2h + s2*C2 + lane*2);
        __half2 u3 = *(const __half2*)(g_h2h + s3*C2 + lane*2);
        for (j += 4; j < jend4; j += 4) {
            int t0 = g_csr[j], t1 = g_csr[j+1], t2 = g_csr[j+2], t3 = g_csr[j+3];
            float b0n = g_as2[t0], b1n = g_as2[t1], b2n = g_as2[t2], b3n = g_as2[t3];
            __half2 v0 = *(const __half2*)(g_h2h + t0*C2 + lane*2);
            __half2 v1 = *(const __half2*)(g_h2h + t1*C2 + lane*2);
            __half2 v2 = *(const __half2*)(g_h2h + t2*C2 + lane*2);
            __half2 v3 = *(const __half2*)(g_h2h + t3*C2 + lane*2);
            float e0 = __expf(lrelu(a0 + ad));
            float e1 = __expf(lrelu(a1 + ad));
            float e2 = __expf(lrelu(a2 + ad));
            float e3 = __expf(lrelu(a3 + ad));
            sum += (e0 + e1) + (e2 + e3);
            float2 f0 = __half22float2(u0), f1 = __half22float2(u1);
            float2 f2 = __half22float2(u2), f3 = __half22float2(u3);
            acc.x += e0 * f0.x + e1 * f1.x + e2 * f2.x + e3 * f3.x;
            acc.y += e0 * f0.y + e1 * f1.y + e2 * f2.y + e3 * f3.y;
            a0 = b0n; a1 = b1n; a2 = b2n; a3 = b3n;
            u0 = v0; u1 = v1; u2 = v2; u3 = v3;
        }
        float e0 = __expf(lrelu(a0 + ad));
        float e1 = __expf(lrelu(a1 + ad));
        float e2 = __expf(lrelu(a2 + ad));
        float e3 = __expf(lrelu(a3 + ad));
        sum += (e0 + e1) + (e2 + e3);
        float2 f0 = __half22float2(u0), f1 = __half22float2(u1);
        float2 f2 = __half22float2(u2), f3 = __half22float2(u3);
        acc.x += e0 * f0.x + e1 * f1.x + e2 * f2.x + e3 * f3.x;
        acc.y += e0 * f0.y + e1 * f1.y + e2 * f2.y + e3 * f3.y;
    }
    for (; j < end; j++) {
        int s = g_csr[j];
        float e = __expf(lrelu(g_as2[s] + ad));
        sum += e;
        float2 f = __half22float2(*(const __half2*)(g_h2h + s * C2 + lane * 2));
        acc.x += e * f.x; acc.y += e * f.y;
    }
    float inv = 1.0f / (sum + 1e-16f);
    float2 bv = *(const float2*)(b2 + lane * 2);
    __half2 o = __floats2half2_rn(elu1(acc.x * inv + bv.x), elu1(acc.y * inv + bv.y));
    *(__half2*)(g_out2h + gw * C2 + lane * 2) = o;
}

// ---------------- fused global mean pool + classifier (1 block per graph) ----------------
__global__ void __launch_bounds__(256) k_poolfinal(
        const int* __restrict__ batch, const float* __restrict__ Wc,
        const float* __restrict__ bc, float* __restrict__ out) {
    __shared__ int sb[2];
    __shared__ float red[4][C2];
    __shared__ float pooled[C2];
    int g = blockIdx.x, tid = threadIdx.x;
    if (tid < 2) {
        int target = g + tid;
        int lo = 0, hi = NN;
        while (lo < hi) { int mid = (lo + hi) >> 1; if (batch[mid] < target) lo = mid + 1; else hi = mid; }
        sb[tid] = lo;
    }
    __syncthreads();
    int lo = sb[0], hi = sb[1];
    int ch = tid & 63, grp = tid >> 6;
    float a0 = 0.f, a1 = 0.f;
    int n = lo + grp;
    for (; n + 4 < hi; n += 8) {
        a0 += __half2float(g_out2h[n * C2 + ch]);
        a1 += __half2float(g_out2h[(n + 4) * C2 + ch]);
    }
    if (n < hi) a0 += __half2float(g_out2h[n * C2 + ch]);
    red[grp][ch] = a0 + a1;
    __syncthreads();
    if (tid < C2) {
        float cnt = (float)(hi - lo); if (cnt < 1.f) cnt = 1.f;
        pooled[tid] = (red[0][tid] + red[1][tid] + red[2][tid] + red[3][tid]) / cnt;
    }
    __syncthreads();
    if (tid < NCLS) {
        float s = 0.f;
        #pragma unroll
        for (int c2 = 0; c2 < C2; c2++) s += pooled[c2] * Wc[c2 * NCLS + tid];
        out[g * NCLS + tid] = s + bc[tid];
    }
}

// ---------------- launch ----------------
extern "C" void kernel_launch(void* const* d_in, const int* in_sizes, int n_in,
                              void* d_out, int out_size) {
    const float* x     = (const float*)d_in[0];
    const int*   ei    = (const int*)  d_in[1];   // [2, E] row-major
    const int*   batch = (const int*)  d_in[2];
    const float* W1    = (const float*)d_in[3];
    const float* atts1 = (const float*)d_in[4];
    const float* attd1 = (const float*)d_in[5];
    const float* b1    = (const float*)d_in[6];
    const float* W2    = (const float*)d_in[7];
    const float* atts2 = (const float*)d_in[8];
    const float* attd2 = (const float*)d_in[9];
    const float* b2    = (const float*)d_in[10];
    const float* Wc    = (const float*)d_in[11];
    const float* bc    = (const float*)d_in[12];
    float* out = (float*)d_out;

    int gemm_grid = (NN + MB - 1) / MB;   // 1563

    // launch order keeps k_scatter at idx 3 (the slot ncu captures) to verify the atomic removal
    k_hist     <<<(EE / 4 + 255) / 256, 256>>>(ei + EE);
    k_scanA    <<<NCHUNK, 256>>>();
    k_scanC    <<<(NN + 511) / 512, 512>>>();
    k_scatter  <<<(SCAT_E4 + NN + 255) / 256, 256>>>(ei);
    k_prepW    <<<(3072 + 255) / 256, 256>>>(W1, W2);
    k_gemm1    <<<gemm_grid, 256>>>(x, atts1, attd1);

    k_agg1     <<<(NN * 32 + 255) / 256, 256>>>(b1);
    k_gemm2    <<<gemm_grid, 128>>>(atts2, attd2);
    k_agg2     <<<(NN * 32 + 255) / 256, 256>>>(b2);

    k_poolfinal<<<NGRAPH, 256>>>(batch, Wc, bc, out);
}